// round 9
// baseline (speedup 1.0000x reference)
#include <cuda_runtime.h>
#include <cuda_bf16.h>
#include <math.h>
#include <stdint.h>

// Problem dims
#define BB 4
#define TT 1024
#define CC 768
#define HH 12
#define LL 6
#define VV 50257
#define DD 64
#define FF 3072
#define MM (BB*TT)        // 4096 rows
#define NQKV 2304
#define VPAD 50304        // 393*128

// ---------------- scratch (device globals; allocation-free) ----------------
__device__ float g_h[(size_t)MM*CC];
__device__ float g_qkv[(size_t)MM*NQKV];
// packed bf16 hi/lo operand buffers: layout [blk128][K/64][r:128][pl:2][64]
__device__ __align__(256) __nv_bfloat16 g_xpk [(size_t)MM*CC*2];
__device__ __align__(256) __nv_bfloat16 g_opk [(size_t)MM*CC*2];
__device__ __align__(256) __nv_bfloat16 g_mpk [(size_t)MM*FF*2];
__device__ __align__(256) __nv_bfloat16 g_wqkvpk[(size_t)NQKV*CC*2];
__device__ __align__(256) __nv_bfloat16 g_wopk  [(size_t)CC*CC*2];
__device__ __align__(256) __nv_bfloat16 g_w1pk  [(size_t)FF*CC*2];
__device__ __align__(256) __nv_bfloat16 g_w2pk  [(size_t)CC*FF*2];
__device__ __align__(256) __nv_bfloat16 g_whpk  [(size_t)VPAD*CC*2];

// ======================= PTX helpers (sm_90 baseline only) =======================
__device__ __forceinline__ uint32_t smem_u32(const void* p) {
    uint32_t a;
    asm("{ .reg .u64 t; cvta.to.shared.u64 t, %1; cvt.u32.u64 %0, t; }"
        : "=r"(a) : "l"(p));
    return a;
}
#define MBAR_INIT(addr, cnt) \
    asm volatile("mbarrier.init.shared.b64 [%0], %1;" :: "r"(addr), "r"((uint32_t)(cnt)) : "memory")
#define MBAR_EXPECT_TX(addr, bytes) \
    asm volatile("mbarrier.arrive.expect_tx.shared.b64 _, [%0], %1;" \
                 :: "r"(addr), "r"((uint32_t)(bytes)) : "memory")

__device__ __forceinline__ void mbar_wait(uint32_t mbar, uint32_t parity) {
    uint32_t done;
    asm volatile(
        "{\n\t.reg .pred p;\n\t"
        "mbarrier.try_wait.parity.acquire.cta.shared::cta.b64 p, [%1], %2;\n\t"
        "selp.b32 %0, 1, 0, p;\n\t}"
        : "=r"(done) : "r"(mbar), "r"(parity) : "memory");
    if (!done) {
        asm volatile(
            "{\n\t.reg .pred P1;\n\t"
            "WAIT_LOOP_%=:\n\t"
            "mbarrier.try_wait.parity.acquire.cta.shared::cta.b64 P1, [%0], %1, 0x989680;\n\t"
            "@P1 bra.uni WAIT_DONE_%=;\n\t"
            "bra.uni WAIT_LOOP_%=;\n\t"
            "WAIT_DONE_%=:\n\t}"
            :: "r"(mbar), "r"(parity) : "memory");
    }
}
__device__ __forceinline__ void bulk_g2s(uint32_t dst, const void* src,
                                         uint32_t bytes, uint32_t mbar) {
    asm volatile(
        "cp.async.bulk.shared::cluster.global.mbarrier::complete_tx::bytes "
        "[%0], [%1], %2, [%3];"
        :: "r"(dst), "l"(src), "r"(bytes), "r"(mbar) : "memory");
}
__device__ __forceinline__ void ldsm4(uint32_t* r, uint32_t addr) {
    asm volatile("ldmatrix.sync.aligned.m8n8.x4.shared.b16 {%0,%1,%2,%3}, [%4];"
        : "=r"(r[0]), "=r"(r[1]), "=r"(r[2]), "=r"(r[3]) : "r"(addr));
}
__device__ __forceinline__ void mma16816(float* d, const uint32_t* a, const uint32_t* b) {
    asm volatile(
        "mma.sync.aligned.m16n8k16.row.col.f32.bf16.bf16.f32 "
        "{%0,%1,%2,%3}, {%4,%5,%6,%7}, {%8,%9}, {%0,%1,%2,%3};"
        : "+f"(d[0]), "+f"(d[1]), "+f"(d[2]), "+f"(d[3])
        : "r"(a[0]), "r"(a[1]), "r"(a[2]), "r"(a[3]), "r"(b[0]), "r"(b[1]));
}

// packed layout helper: element index for (blk128, kc, r, pl, kk)
__device__ __forceinline__ size_t pk_rowseg(int KC, int blk, int kc, int r) {
    return ((size_t)(blk * KC + kc) * 128 + r) * 128;
}
__device__ __forceinline__ int pk_within(int r, int kk) {
    int ch = kk >> 3, w8 = kk & 7;
    return ((ch ^ (r & 7)) << 3) + w8;
}

// ======================= small kernels =======================
__global__ void embed_kernel(const int* __restrict__ tok,
                             const float* __restrict__ wte,
                             const float* __restrict__ wpe,
                             float* __restrict__ h) {
    int bt = blockIdx.x;
    int t  = bt % TT;
    int tk = tok[bt];
    const float* we = wte + (size_t)tk * CC;
    const float* wp = wpe + (size_t)t  * CC;
    float* hr = h + (size_t)bt * CC;
    for (int c = threadIdx.x; c < CC; c += blockDim.x)
        hr[c] = we[c] + wp[c];
}

// LayerNorm producing packed bf16 hi/lo A-operand (KC = CC/64 = 12)
__global__ void ln_pk_kernel(const float* __restrict__ x,
                             const float* __restrict__ gamma,
                             const float* __restrict__ beta,
                             __nv_bfloat16* __restrict__ outpk) {
    int row = blockIdx.x;
    const float* xr = x + (size_t)row * CC;
    __shared__ float red[256];
    int tid = threadIdx.x;

    float s = 0.f;
    for (int c = tid; c < CC; c += 256) s += xr[c];
    red[tid] = s; __syncthreads();
    for (int o = 128; o > 0; o >>= 1) {
        if (tid < o) red[tid] += red[tid + o];
        __syncthreads();
    }
    float mu = red[0] * (1.0f / CC);
    __syncthreads();

    float v = 0.f;
    for (int c = tid; c < CC; c += 256) { float d = xr[c] - mu; v += d * d; }
    red[tid] = v; __syncthreads();
    for (int o = 128; o > 0; o >>= 1) {
        if (tid < o) red[tid] += red[tid + o];
        __syncthreads();
    }
    float rstd = rsqrtf(red[0] * (1.0f / CC) + 1e-5f);

    int blk = row >> 7, r = row & 127;
    for (int c = tid; c < CC; c += 256) {
        float val = (xr[c] - mu) * rstd * gamma[c] + beta[c];
        __nv_bfloat16 hi = __float2bfloat16(val);
        __nv_bfloat16 lo = __float2bfloat16(val - __bfloat162float(hi));
        size_t base = pk_rowseg(12, blk, c >> 6, r);
        int w = pk_within(r, c & 63);
        outpk[base + w]      = hi;
        outpk[base + 64 + w] = lo;
    }
}

// transpose + convert + split weight W[K,N](fp32) -> packed layout
__global__ __launch_bounds__(256)
void pack_w_kernel(const float* __restrict__ W, __nv_bfloat16* __restrict__ Bpk,
                   int K, int N, int n0out) {
    __shared__ float sm[64][65];
    int tid = threadIdx.x;
    int n0 = blockIdx.x * 64;
    int k0 = blockIdx.y * 64;
    int KC = K >> 6;

    for (int idx = tid; idx < 64 * 64; idx += 256) {
        int kr = idx >> 6, nc = idx & 63;
        int gn = n0 + nc;
        sm[kr][nc] = (gn < N) ? W[(size_t)(k0 + kr) * N + gn] : 0.f;
    }
    __syncthreads();

    for (int g = tid; g < 512; g += 256) {
        int n = g >> 3, ch = g & 7;
        int gn = n0out + n0 + n;
        int bn = gn >> 7, r = gn & 127;
        size_t base = pk_rowseg(KC, bn, blockIdx.y, r);
        int w = (ch ^ (r & 7)) << 3;
        union { uint4 v; __nv_bfloat16 b[8]; } uh, ul;
#pragma unroll
        for (int j = 0; j < 8; ++j) {
            float x = sm[ch * 8 + j][n];
            __nv_bfloat16 hi = __float2bfloat16(x);
            uh.b[j] = hi;
            ul.b[j] = __float2bfloat16(x - __bfloat162float(hi));
        }
        *(uint4*)(Bpk + base + w)      = uh.v;
        *(uint4*)(Bpk + base + 64 + w) = ul.v;
    }
}

// ======================= HMMA GEMM (mma.sync bf16 x3 split) =======================
#define EPI_NONE 0
#define EPI_BIAS 1
#define EPI_GELU_PK 2
#define EPI_RES 3

#define STAGES 3
#define STAGE_BYTES 65536   // A 32K | B 32K  (BK=64)
#define HG_SMEM (STAGES * STAGE_BYTES)

// 512 threads, 16 warps in 4(M) x 4(N) grid; warp tile 32x32.
template<int EPI>
__global__ __launch_bounds__(512, 1)
void hgemm(const __nv_bfloat16* __restrict__ Apk,
           const __nv_bfloat16* __restrict__ Bpk,
           const float* __restrict__ bias,
           const float* __restrict__ Res,
           float* __restrict__ outf,
           __nv_bfloat16* __restrict__ outpk,
           int N, int K, int Nl) {
    extern __shared__ __align__(1024) char smem[];
    __shared__ __align__(8) uint64_t s_full[STAGES];

    int tid = threadIdx.x;
    int lane = tid & 31, w = tid >> 5;
    int wm = w & 3, wn = w >> 2;      // warp grid 4(M) x 4(N)
    int bm = blockIdx.y, bn = blockIdx.x;
    int KC = K >> 6;
    uint32_t sbase = smem_u32(smem);
    uint32_t mb0 = smem_u32(&s_full[0]);

    if (tid == 0) {
#pragma unroll
        for (int s = 0; s < STAGES; ++s) MBAR_INIT(mb0 + s * 8, 1);
    }
    __syncthreads();

    float acc[2][4][4];
#pragma unroll
    for (int i = 0; i < 2; ++i)
#pragma unroll
        for (int j = 0; j < 4; ++j)
#pragma unroll
            for (int q = 0; q < 4; ++q) acc[i][j][q] = 0.f;

    const int la15 = lane & 15, lahi = lane >> 4;
    const int bmx = lane >> 3;
    const int brow_base = wn * 32 + ((bmx >> 1) << 3) + (lane & 7);
    const int bcs = bmx & 1;

    const int nc = KC;
    const size_t CHUNK = 16384;   // bf16 elements per 32KB block

    if (tid == 0) {
#pragma unroll
        for (int c = 0; c < STAGES - 1; ++c) {
            uint32_t m = mb0 + c * 8;
            MBAR_EXPECT_TX(m, STAGE_BYTES);
            bulk_g2s(sbase + c * STAGE_BYTES,
                     Apk + ((size_t)bm * KC + c) * CHUNK, 32768, m);
            bulk_g2s(sbase + c * STAGE_BYTES + 32768,
                     Bpk + ((size_t)bn * KC + c) * CHUNK, 32768, m);
        }
    }

    for (int c = 0; c < nc; ++c) {
        int s = c % STAGES;
        mbar_wait(mb0 + s * 8, (c / STAGES) & 1);

        if (tid == 0) {
            int cn = c + STAGES - 1;
            if (cn < nc) {
                int sn = cn % STAGES;
                uint32_t m = mb0 + sn * 8;
                MBAR_EXPECT_TX(m, STAGE_BYTES);
                bulk_g2s(sbase + sn * STAGE_BYTES,
                         Apk + ((size_t)bm * KC + cn) * CHUNK, 32768, m);
                bulk_g2s(sbase + sn * STAGE_BYTES + 32768,
                         Bpk + ((size_t)bn * KC + cn) * CHUNK, 32768, m);
            }
        }

        uint32_t Ab = sbase + s * STAGE_BYTES;
        uint32_t Bb = Ab + 32768;

#pragma unroll
        for (int kh = 0; kh < 4; ++kh) {
            uint32_t af[2][2][4];     // [pl][im][4]
            uint32_t bf_[2][4][2];    // [pl][in_][2]
#pragma unroll
            for (int im = 0; im < 2; ++im) {
                int r = wm * 32 + im * 16 + la15;
                int cch = kh * 2 + lahi;
                uint32_t off = (uint32_t)(r * 256 + (((cch ^ (r & 7))) << 4));
                ldsm4(af[0][im], Ab + off);
                ldsm4(af[1][im], Ab + off + 128);
            }
#pragma unroll
            for (int g2 = 0; g2 < 2; ++g2) {
                int nr = brow_base + g2 * 16;
                int cch = kh * 2 + bcs;
                uint32_t off = (uint32_t)(nr * 256 + (((cch ^ (nr & 7))) << 4));
#pragma unroll
                for (int pl = 0; pl < 2; ++pl) {
                    uint32_t t4[4];
                    ldsm4(t4, Bb + off + pl * 128);
                    bf_[pl][g2 * 2][0]     = t4[0];
                    bf_[pl][g2 * 2][1]     = t4[1];
                    bf_[pl][g2 * 2 + 1][0] = t4[2];
                    bf_[pl][g2 * 2 + 1][1] = t4[3];
                }
            }
#pragma unroll
            for (int im = 0; im < 2; ++im)
#pragma unroll
                for (int in_ = 0; in_ < 4; ++in_) {
                    mma16816(acc[im][in_], af[0][im], bf_[0][in_]);
                    mma16816(acc[im][in_], af[0][im], bf_[1][in_]);
                    mma16816(acc[im][in_], af[1][im], bf_[0][in_]);
                }
        }
        __syncthreads();
    }

    // ---------------- epilogue ----------------
    int r0 = bm * 128 + wm * 32 + (lane >> 2);
    int c0base = bn * 128 + wn * 32 + 2 * (lane & 3);
    int KCo = N >> 6;

#pragma unroll
    for (int im = 0; im < 2; ++im) {
#pragma unroll
        for (int half = 0; half < 2; ++half) {
            int row = r0 + im * 16 + half * 8;
#pragma unroll
            for (int in_ = 0; in_ < 4; ++in_) {
                int col = c0base + in_ * 8;
                float v0 = acc[im][in_][half * 2 + 0];
                float v1 = acc[im][in_][half * 2 + 1];
                if (EPI == EPI_NONE) {
                    *(float2*)(outf + (size_t)row * Nl + col) = make_float2(v0, v1);
                } else if (EPI == EPI_RES) {
                    const float* rr = Res + (size_t)row * Nl + col;
                    v0 += bias[col]     + rr[0];
                    v1 += bias[col + 1] + rr[1];
                    *(float2*)(outf + (size_t)row * Nl + col) = make_float2(v0, v1);
                } else if (EPI == EPI_BIAS) {
                    if (col < Nl)     outf[(size_t)row * Nl + col]     = v0 + bias[col];
                    if (col + 1 < Nl) outf[(size_t)row * Nl + col + 1] = v1 + bias[col + 1];
                } else if (EPI == EPI_GELU_PK) {
                    v0 += bias[col];
                    v1 += bias[col + 1];
                    v0 = 0.5f * v0 * (1.0f + erff(v0 * 0.7071067811865476f));
                    v1 = 0.5f * v1 * (1.0f + erff(v1 * 0.7071067811865476f));
                    __nv_bfloat16 h0 = __float2bfloat16(v0);
                    __nv_bfloat16 h1 = __float2bfloat16(v1);
                    __nv_bfloat16 l0 = __float2bfloat16(v0 - __bfloat162float(h0));
                    __nv_bfloat16 l1 = __float2bfloat16(v1 - __bfloat162float(h1));
                    int blk = row >> 7, r = row & 127;
                    size_t base = pk_rowseg(KCo, blk, col >> 6, r);
                    int wi = pk_within(r, col & 63);
                    *(__nv_bfloat162*)(outpk + base + wi) =
                        __nv_bfloat162(h0, h1);
                    *(__nv_bfloat162*)(outpk + base + 64 + wi) =
                        __nv_bfloat162(l0, l1);
                }
            }
        }
    }
}

// ---------------- tiled causal attention: 64 q-rows per block ----------------
#define ATT_PAD 68
#define ATT_ROW (64 * ATT_PAD)
#define ATT_SMEM (4 * ATT_ROW * 4)

__global__ __launch_bounds__(256)
void attn_kernel(const float* __restrict__ QKV,
                 __nv_bfloat16* __restrict__ Opk) {
    extern __shared__ float asm_[];
    float* sq = asm_;
    float* sk = asm_ + ATT_ROW;
    float* sv = asm_ + 2 * ATT_ROW;
    float* sp = asm_ + 3 * ATT_ROW;

    int tid = threadIdx.x;
    int q0 = blockIdx.x * 64;
    int hh = blockIdx.y;
    int b  = blockIdx.z;
    int qr = tid >> 2, dg = tid & 3;
    int qg = q0 + qr;

    const float scale = rsqrtf((float)CC);

    {
        int r = tid >> 4, c4 = (tid & 15) * 4;
#pragma unroll
        for (int it = 0; it < 4; ++it, r += 16) {
            *(float4*)&sq[r * ATT_PAD + c4] =
                *(const float4*)(QKV + ((size_t)(b * TT + q0 + r)) * NQKV + hh * DD + c4);
        }
    }

    float m = -INFINITY, l = 0.f;
    float acc[16];
#pragma unroll
    for (int i = 0; i < 16; ++i) acc[i] = 0.f;

    for (int j0 = 0; j0 <= q0; j0 += 64) {
        __syncthreads();
        {
            int r = tid >> 4, c4 = (tid & 15) * 4;
#pragma unroll
            for (int it = 0; it < 4; ++it, r += 16) {
                size_t rb = ((size_t)(b * TT + j0 + r)) * NQKV + hh * DD + c4;
                *(float4*)&sk[r * ATT_PAD + c4] = *(const float4*)(QKV + rb + CC);
                *(float4*)&sv[r * ATT_PAD + c4] = *(const float4*)(QKV + rb + 2 * CC);
            }
        }
        __syncthreads();

        float s[16];
#pragma unroll
        for (int jj = 0; jj < 16; ++jj) s[jj] = 0.f;
        const float* qrow = sq + qr * ATT_PAD;
#pragma unroll
        for (int k4 = 0; k4 < 16; ++k4) {
            float4 qv = *(const float4*)(qrow + k4 * 4);
#pragma unroll
            for (int jj = 0; jj < 16; ++jj) {
                int j = jj * 4 + dg;
                float4 kv = *(const float4*)(sk + j * ATT_PAD + k4 * 4);
                s[jj] = fmaf(qv.x, kv.x, s[jj]);
                s[jj] = fmaf(qv.y, kv.y, s[jj]);
                s[jj] = fmaf(qv.z, kv.z, s[jj]);
                s[jj] = fmaf(qv.w, kv.w, s[jj]);
            }
        }

        float tmax = -INFINITY;
#pragma unroll
        for (int jj = 0; jj < 16; ++jj) {
            int j = jj * 4 + dg;
            s[jj] = (j0 + j <= qg) ? s[jj] * scale : -INFINITY;
            tmax = fmaxf(tmax, s[jj]);
        }
        tmax = fmaxf(tmax, __shfl_xor_sync(0xFFFFFFFF, tmax, 1));
        tmax = fmaxf(tmax, __shfl_xor_sync(0xFFFFFFFF, tmax, 2));

        float newm = fmaxf(m, tmax);
        float corr = __expf(m - newm);
        float lp = 0.f;
#pragma unroll
        for (int jj = 0; jj < 16; ++jj) {
            int j = jj * 4 + dg;
            float p = __expf(s[jj] - newm);
            sp[qr * ATT_PAD + j] = p;
            lp += p;
        }
        lp += __shfl_xor_sync(0xFFFFFFFF, lp, 1);
        lp += __shfl_xor_sync(0xFFFFFFFF, lp, 2);
        l = l * corr + lp;
        m = newm;
#pragma unroll
        for (int i = 0; i < 16; ++i) acc[i] *= corr;

        __syncthreads();

        const float* prow = sp + qr * ATT_PAD;
#pragma unroll 8
        for (int j = 0; j < 64; ++j) {
            float pj = prow[j];
            const float* vrow = sv + j * ATT_PAD + dg * 16;
            float4 v0 = *(const float4*)(vrow);
            float4 v1 = *(const float4*)(vrow + 4);
            float4 v2 = *(const float4*)(vrow + 8);
            float4 v3 = *(const float4*)(vrow + 12);
            acc[0]  = fmaf(pj, v0.x, acc[0]);  acc[1]  = fmaf(pj, v0.y, acc[1]);
            acc[2]  = fmaf(pj, v0.z, acc[2]);  acc[3]  = fmaf(pj, v0.w, acc[3]);
            acc[4]  = fmaf(pj, v1.x, acc[4]);  acc[5]  = fmaf(pj, v1.y, acc[5]);
            acc[6]  = fmaf(pj, v1.z, acc[6]);  acc[7]  = fmaf(pj, v1.w, acc[7]);
            acc[8]  = fmaf(pj, v2.x, acc[8]);  acc[9]  = fmaf(pj, v2.y, acc[9]);
            acc[10] = fmaf(pj, v2.z, acc[10]); acc[11] = fmaf(pj, v2.w, acc[11]);
            acc[12] = fmaf(pj, v3.x, acc[12]); acc[13] = fmaf(pj, v3.y, acc[13]);
            acc[14] = fmaf(pj, v3.z, acc[14]); acc[15] = fmaf(pj, v3.w, acc[15]);
        }
    }

    float inv = 1.0f / l;
    int rowg = b * TT + qg;
    int blk = rowg >> 7, r = rowg & 127;
    size_t base = pk_rowseg(12, blk, hh, r);
#pragma unroll
    for (int dd = 0; dd < 16; dd += 2) {
        int d = dg * 16 + dd;
        float v0 = acc[dd] * inv;
        float v1 = acc[dd + 1] * inv;
        __nv_bfloat16 h0 = __float2bfloat16(v0);
        __nv_bfloat16 h1 = __float2bfloat16(v1);
        __nv_bfloat16 l0 = __float2bfloat16(v0 - __bfloat162float(h0));
        __nv_bfloat16 l1 = __float2bfloat16(v1 - __bfloat162float(h1));
        int wi = pk_within(r, d);
        *(__nv_bfloat162*)(Opk + base + wi)      = __nv_bfloat162(h0, h1);
        *(__nv_bfloat162*)(Opk + base + 64 + wi) = __nv_bfloat162(l0, l1);
    }
}

// ======================= launch =======================
extern "C" void kernel_launch(void* const* d_in, const int* in_sizes, int n_in,
                              void* d_out, int out_size) {
    const int*   tokens = (const int*)  d_in[0];
    const float* wte    = (const float*)d_in[1];
    const float* wpe    = (const float*)d_in[2];
    const float* Wq     = (const float*)d_in[3];
    const float* Wk     = (const float*)d_in[4];
    const float* Wv     = (const float*)d_in[5];
    const float* Wo     = (const float*)d_in[6];
    const float* bo     = (const float*)d_in[7];
    const float* ln1g   = (const float*)d_in[8];
    const float* ln1b   = (const float*)d_in[9];
    const float* ln2g   = (const float*)d_in[10];
    const float* ln2b   = (const float*)d_in[11];
    const float* W1     = (const float*)d_in[12];
    const float* b1     = (const float*)d_in[13];
    const float* W2     = (const float*)d_in[14];
    const float* b2     = (const float*)d_in[15];
    const float* lnfg   = (const float*)d_in[16];
    const float* lnfb   = (const float*)d_in[17];
    const float* Wh     = (const float*)d_in[18];
    const float* bh     = (const float*)d_in[19];
    float* out = (float*)d_out;

    static bool attrs_set = false;
    if (!attrs_set) {
        cudaFuncSetAttribute(hgemm<EPI_NONE>,    cudaFuncAttributeMaxDynamicSharedMemorySize, HG_SMEM);
        cudaFuncSetAttribute(hgemm<EPI_BIAS>,    cudaFuncAttributeMaxDynamicSharedMemorySize, HG_SMEM);
        cudaFuncSetAttribute(hgemm<EPI_GELU_PK>, cudaFuncAttributeMaxDynamicSharedMemorySize, HG_SMEM);
        cudaFuncSetAttribute(hgemm<EPI_RES>,     cudaFuncAttributeMaxDynamicSharedMemorySize, HG_SMEM);
        cudaFuncSetAttribute(attn_kernel,        cudaFuncAttributeMaxDynamicSharedMemorySize, ATT_SMEM);
        attrs_set = true;
    }

    float *h, *qkv;
    __nv_bfloat16 *xpk, *opk, *mpk, *wqkvpk, *wopk, *w1pk, *w2pk, *whpk;
    cudaGetSymbolAddress((void**)&h,      g_h);
    cudaGetSymbolAddress((void**)&qkv,    g_qkv);
    cudaGetSymbolAddress((void**)&xpk,    g_xpk);
    cudaGetSymbolAddress((void**)&opk,    g_opk);
    cudaGetSymbolAddress((void**)&mpk,    g_mpk);
    cudaGetSymbolAddress((void**)&wqkvpk, g_wqkvpk);
    cudaGetSymbolAddress((void**)&wopk,   g_wopk);
    cudaGetSymbolAddress((void**)&w1pk,   g_w1pk);
    cudaGetSymbolAddress((void**)&w2pk,   g_w2pk);
    cudaGetSymbolAddress((void**)&whpk,   g_whpk);

    dim3 gQKV(NQKV / 128, MM / 128);   // (18, 32)
    dim3 gC(CC / 128, MM / 128);       // (6, 32)
    dim3 gF(FF / 128, MM / 128);       // (24, 32)
    dim3 gV(VPAD / 128, MM / 128);     // (393, 32)

    dim3 pCC(12, 12);
    dim3 pW1(48, 12);
    dim3 pW2(12, 48);
    dim3 pWh(786, 12);

    embed_kernel<<<MM, 256>>>(tokens, wte, wpe, h);
    pack_w_kernel<<<pWh, 256>>>(Wh, whpk, CC, VV, 0);

    for (int l = 0; l < LL; l++) {
        pack_w_kernel<<<pCC, 256>>>(Wq + (size_t)l * CC * CC, wqkvpk, CC, CC, 0);
        pack_w_kernel<<<pCC, 256>>>(Wk + (size_t)l * CC * CC, wqkvpk, CC, CC, 768);
        pack_w_kernel<<<pCC, 256>>>(Wv + (size_t)l * CC * CC, wqkvpk, CC, CC, 1536);
        pack_w_kernel<<<pCC, 256>>>(Wo + (size_t)l * CC * CC, wopk, CC, CC, 0);
        pack_w_kernel<<<pW1, 256>>>(W1 + (size_t)l * CC * FF, w1pk, CC, FF, 0);
        pack_w_kernel<<<pW2, 256>>>(W2 + (size_t)l * FF * CC, w2pk, FF, CC, 0);

        ln_pk_kernel<<<MM, 256>>>(h, ln1g + l * CC, ln1b + l * CC, xpk);
        hgemm<EPI_NONE><<<gQKV, 512, HG_SMEM>>>(xpk, wqkvpk, nullptr, nullptr,
                                                qkv, nullptr, NQKV, CC, NQKV);

        attn_kernel<<<dim3(TT / 64, HH, BB), 256, ATT_SMEM>>>(qkv, opk);

        hgemm<EPI_RES><<<gC, 512, HG_SMEM>>>(opk, wopk, bo + l * CC, h,
                                             h, nullptr, CC, CC, CC);

        ln_pk_kernel<<<MM, 256>>>(h, ln2g + l * CC, ln2b + l * CC, xpk);
        hgemm<EPI_GELU_PK><<<gF, 512, HG_SMEM>>>(xpk, w1pk, b1 + l * FF, nullptr,
                                                 nullptr, mpk, FF, CC, FF);
        hgemm<EPI_RES><<<gC, 512, HG_SMEM>>>(mpk, w2pk, b2 + l * CC, h,
                                             h, nullptr, CC, FF, CC);
    }

    ln_pk_kernel<<<MM, 256>>>(h, lnfg, lnfb, xpk);
    hgemm<EPI_BIAS><<<gV, 512, HG_SMEM>>>(xpk, whpk, bh, nullptr,
                                          out, nullptr, VPAD, CC, VV);
}

// round 11
// speedup vs baseline: 1.1215x; 1.1215x over previous
#include <cuda_runtime.h>
#include <cuda_bf16.h>
#include <cuda_fp16.h>
#include <math.h>
#include <stdint.h>

// Problem dims
#define BB 4
#define TT 1024
#define CC 768
#define HH 12
#define LL 6
#define VV 50257
#define DD 64
#define FF 3072
#define MM (BB*TT)        // 4096 rows
#define NQKV 2304
#define VPAD 50304        // 393*128

// ---------------- scratch (device globals; allocation-free) ----------------
__device__ float g_h[(size_t)MM*CC];
__device__ float g_qkv[(size_t)MM*NQKV];
// packed bf16 hi/lo operand buffers: layout [blk128][K/64][r:128][pl:2][64]
__device__ __align__(256) __nv_bfloat16 g_xpk [(size_t)MM*CC*2];   // also used as fp16 for head
__device__ __align__(256) __nv_bfloat16 g_opk [(size_t)MM*CC*2];
__device__ __align__(256) __nv_bfloat16 g_mpk [(size_t)MM*FF*2];
__device__ __align__(256) __nv_bfloat16 g_wqkvpk[(size_t)NQKV*CC*2];
__device__ __align__(256) __nv_bfloat16 g_wopk  [(size_t)CC*CC*2];
__device__ __align__(256) __nv_bfloat16 g_w1pk  [(size_t)FF*CC*2];
__device__ __align__(256) __nv_bfloat16 g_w2pk  [(size_t)CC*FF*2];
__device__ __align__(256) __nv_bfloat16 g_whpk  [(size_t)VPAD*CC*2]; // fp16 single plane uses half

// ======================= PTX helpers (sm_90 baseline only) =======================
__device__ __forceinline__ uint32_t smem_u32(const void* p) {
    uint32_t a;
    asm("{ .reg .u64 t; cvta.to.shared.u64 t, %1; cvt.u32.u64 %0, t; }"
        : "=r"(a) : "l"(p));
    return a;
}
#define MBAR_INIT(addr, cnt) \
    asm volatile("mbarrier.init.shared.b64 [%0], %1;" :: "r"(addr), "r"((uint32_t)(cnt)) : "memory")
#define MBAR_EXPECT_TX(addr, bytes) \
    asm volatile("mbarrier.arrive.expect_tx.shared.b64 _, [%0], %1;" \
                 :: "r"(addr), "r"((uint32_t)(bytes)) : "memory")

__device__ __forceinline__ void mbar_wait(uint32_t mbar, uint32_t parity) {
    uint32_t done;
    asm volatile(
        "{\n\t.reg .pred p;\n\t"
        "mbarrier.try_wait.parity.acquire.cta.shared::cta.b64 p, [%1], %2;\n\t"
        "selp.b32 %0, 1, 0, p;\n\t}"
        : "=r"(done) : "r"(mbar), "r"(parity) : "memory");
    if (!done) {
        asm volatile(
            "{\n\t.reg .pred P1;\n\t"
            "WAIT_LOOP_%=:\n\t"
            "mbarrier.try_wait.parity.acquire.cta.shared::cta.b64 P1, [%0], %1, 0x989680;\n\t"
            "@P1 bra.uni WAIT_DONE_%=;\n\t"
            "bra.uni WAIT_LOOP_%=;\n\t"
            "WAIT_DONE_%=:\n\t}"
            :: "r"(mbar), "r"(parity) : "memory");
    }
}
__device__ __forceinline__ void bulk_g2s(uint32_t dst, const void* src,
                                         uint32_t bytes, uint32_t mbar) {
    asm volatile(
        "cp.async.bulk.shared::cluster.global.mbarrier::complete_tx::bytes "
        "[%0], [%1], %2, [%3];"
        :: "r"(dst), "l"(src), "r"(bytes), "r"(mbar) : "memory");
}
__device__ __forceinline__ void ldsm4(uint32_t* r, uint32_t addr) {
    asm volatile("ldmatrix.sync.aligned.m8n8.x4.shared.b16 {%0,%1,%2,%3}, [%4];"
        : "=r"(r[0]), "=r"(r[1]), "=r"(r[2]), "=r"(r[3]) : "r"(addr));
}
__device__ __forceinline__ void mma16816(float* d, const uint32_t* a, const uint32_t* b) {
    asm volatile(
        "mma.sync.aligned.m16n8k16.row.col.f32.bf16.bf16.f32 "
        "{%0,%1,%2,%3}, {%4,%5,%6,%7}, {%8,%9}, {%0,%1,%2,%3};"
        : "+f"(d[0]), "+f"(d[1]), "+f"(d[2]), "+f"(d[3])
        : "r"(a[0]), "r"(a[1]), "r"(a[2]), "r"(a[3]), "r"(b[0]), "r"(b[1]));
}
__device__ __forceinline__ void mma16816h(float* d, const uint32_t* a, const uint32_t* b) {
    asm volatile(
        "mma.sync.aligned.m16n8k16.row.col.f32.f16.f16.f32 "
        "{%0,%1,%2,%3}, {%4,%5,%6,%7}, {%8,%9}, {%0,%1,%2,%3};"
        : "+f"(d[0]), "+f"(d[1]), "+f"(d[2]), "+f"(d[3])
        : "r"(a[0]), "r"(a[1]), "r"(a[2]), "r"(a[3]), "r"(b[0]), "r"(b[1]));
}

// packed layout helper: element index for (blk128, kc, r, pl, kk)
__device__ __forceinline__ size_t pk_rowseg(int KC, int blk, int kc, int r) {
    return ((size_t)(blk * KC + kc) * 128 + r) * 128;
}
__device__ __forceinline__ int pk_within(int r, int kk) {
    int ch = kk >> 3, w8 = kk & 7;
    return ((ch ^ (r & 7)) << 3) + w8;
}

// ======================= small kernels =======================
__global__ void embed_kernel(const int* __restrict__ tok,
                             const float* __restrict__ wte,
                             const float* __restrict__ wpe,
                             float* __restrict__ h) {
    int bt = blockIdx.x;
    int t  = bt % TT;
    int tk = tok[bt];
    const float* we = wte + (size_t)tk * CC;
    const float* wp = wpe + (size_t)t  * CC;
    float* hr = h + (size_t)bt * CC;
    for (int c = threadIdx.x; c < CC; c += blockDim.x)
        hr[c] = we[c] + wp[c];
}

// LayerNorm producing packed bf16 hi/lo A-operand (KC = CC/64 = 12)
__global__ void ln_pk_kernel(const float* __restrict__ x,
                             const float* __restrict__ gamma,
                             const float* __restrict__ beta,
                             __nv_bfloat16* __restrict__ outpk) {
    int row = blockIdx.x;
    const float* xr = x + (size_t)row * CC;
    __shared__ float red[256];
    int tid = threadIdx.x;

    float s = 0.f;
    for (int c = tid; c < CC; c += 256) s += xr[c];
    red[tid] = s; __syncthreads();
    for (int o = 128; o > 0; o >>= 1) {
        if (tid < o) red[tid] += red[tid + o];
        __syncthreads();
    }
    float mu = red[0] * (1.0f / CC);
    __syncthreads();

    float v = 0.f;
    for (int c = tid; c < CC; c += 256) { float d = xr[c] - mu; v += d * d; }
    red[tid] = v; __syncthreads();
    for (int o = 128; o > 0; o >>= 1) {
        if (tid < o) red[tid] += red[tid + o];
        __syncthreads();
    }
    float rstd = rsqrtf(red[0] * (1.0f / CC) + 1e-5f);

    int blk = row >> 7, r = row & 127;
    for (int c = tid; c < CC; c += 256) {
        float val = (xr[c] - mu) * rstd * gamma[c] + beta[c];
        __nv_bfloat16 hi = __float2bfloat16(val);
        __nv_bfloat16 lo = __float2bfloat16(val - __bfloat162float(hi));
        size_t base = pk_rowseg(12, blk, c >> 6, r);
        int w = pk_within(r, c & 63);
        outpk[base + w]      = hi;
        outpk[base + 64 + w] = lo;
    }
}

// LayerNorm producing packed fp16 hi/lo A-operand (for LM head)
__global__ void ln_pk16_kernel(const float* __restrict__ x,
                               const float* __restrict__ gamma,
                               const float* __restrict__ beta,
                               __half* __restrict__ outpk) {
    int row = blockIdx.x;
    const float* xr = x + (size_t)row * CC;
    __shared__ float red[256];
    int tid = threadIdx.x;

    float s = 0.f;
    for (int c = tid; c < CC; c += 256) s += xr[c];
    red[tid] = s; __syncthreads();
    for (int o = 128; o > 0; o >>= 1) {
        if (tid < o) red[tid] += red[tid + o];
        __syncthreads();
    }
    float mu = red[0] * (1.0f / CC);
    __syncthreads();

    float v = 0.f;
    for (int c = tid; c < CC; c += 256) { float d = xr[c] - mu; v += d * d; }
    red[tid] = v; __syncthreads();
    for (int o = 128; o > 0; o >>= 1) {
        if (tid < o) red[tid] += red[tid + o];
        __syncthreads();
    }
    float rstd = rsqrtf(red[0] * (1.0f / CC) + 1e-5f);

    int blk = row >> 7, r = row & 127;
    for (int c = tid; c < CC; c += 256) {
        float val = (xr[c] - mu) * rstd * gamma[c] + beta[c];
        __half hi = __float2half_rn(val);
        __half lo = __float2half_rn(val - __half2float(hi));
        size_t base = pk_rowseg(12, blk, c >> 6, r);
        int w = pk_within(r, c & 63);
        outpk[base + w]      = hi;
        outpk[base + 64 + w] = lo;
    }
}

// transpose + convert + split weight W[K,N](fp32) -> packed bf16 hi/lo layout
__global__ __launch_bounds__(256)
void pack_w_kernel(const float* __restrict__ W, __nv_bfloat16* __restrict__ Bpk,
                   int K, int N, int n0out) {
    __shared__ float sm[64][65];
    int tid = threadIdx.x;
    int n0 = blockIdx.x * 64;
    int k0 = blockIdx.y * 64;
    int KC = K >> 6;

    for (int idx = tid; idx < 64 * 64; idx += 256) {
        int kr = idx >> 6, nc = idx & 63;
        int gn = n0 + nc;
        sm[kr][nc] = (gn < N) ? W[(size_t)(k0 + kr) * N + gn] : 0.f;
    }
    __syncthreads();

    for (int g = tid; g < 512; g += 256) {
        int n = g >> 3, ch = g & 7;
        int gn = n0out + n0 + n;
        int bn = gn >> 7, r = gn & 127;
        size_t base = pk_rowseg(KC, bn, blockIdx.y, r);
        int w = (ch ^ (r & 7)) << 3;
        union { uint4 v; __nv_bfloat16 b[8]; } uh, ul;
#pragma unroll
        for (int j = 0; j < 8; ++j) {
            float x = sm[ch * 8 + j][n];
            __nv_bfloat16 hi = __float2bfloat16(x);
            uh.b[j] = hi;
            ul.b[j] = __float2bfloat16(x - __bfloat162float(hi));
        }
        *(uint4*)(Bpk + base + w)      = uh.v;
        *(uint4*)(Bpk + base + 64 + w) = ul.v;
    }
}

// transpose + convert weight W[K,N](fp32) -> packed fp16 SINGLE-plane layout
// rowseg = 64 halfs per (r,kc): base = ((bn*KC+kc)*128 + r)*64
__global__ __launch_bounds__(256)
void pack_w16_kernel(const float* __restrict__ W, __half* __restrict__ Bpk,
                     int K, int N) {
    __shared__ float sm[64][65];
    int tid = threadIdx.x;
    int n0 = blockIdx.x * 64;
    int k0 = blockIdx.y * 64;
    int KC = K >> 6;

    for (int idx = tid; idx < 64 * 64; idx += 256) {
        int kr = idx >> 6, nc = idx & 63;
        int gn = n0 + nc;
        sm[kr][nc] = (gn < N) ? W[(size_t)(k0 + kr) * N + gn] : 0.f;
    }
    __syncthreads();

    for (int g = tid; g < 512; g += 256) {
        int n = g >> 3, ch = g & 7;
        int gn = n0 + n;
        int bn = gn >> 7, r = gn & 127;
        size_t base = ((size_t)(bn * KC + blockIdx.y) * 128 + r) * 64;
        int w = (ch ^ (r & 7)) << 3;
        union { uint4 v; __half b[8]; } uh;
#pragma unroll
        for (int j = 0; j < 8; ++j)
            uh.b[j] = __float2half_rn(sm[ch * 8 + j][n]);
        *(uint4*)(Bpk + base + w) = uh.v;
    }
}

// ======================= HMMA GEMM (mma.sync bf16 x3 split) =======================
#define EPI_NONE 0
#define EPI_BIAS 1
#define EPI_GELU_PK 2
#define EPI_RES 3

#define STAGES 3
// IMS = 4 -> BM 128 (A chunk 32KB); IMS = 2 -> BM 64 (A chunk 16KB). B chunk 32KB.
#define HG_SMEM_128 (STAGES * (32768 + 32768))
#define HG_SMEM_64  (STAGES * (16384 + 32768))

template<int EPI, int IMS>
__global__ __launch_bounds__(256, 1)
void hgemm(const __nv_bfloat16* __restrict__ Apk,
           const __nv_bfloat16* __restrict__ Bpk,
           const float* __restrict__ bias,
           const float* __restrict__ Res,
           float* __restrict__ outf,
           __nv_bfloat16* __restrict__ outpk,
           int N, int K, int Nl) {
    constexpr int ABYTES = IMS * 8192;
    constexpr int SSTRIDE = ABYTES + 32768;
    extern __shared__ __align__(1024) char smem[];
    __shared__ __align__(8) uint64_t s_full[STAGES];

    int tid = threadIdx.x;
    int lane = tid & 31, w = tid >> 5;
    int wm = w & 1, wn = w >> 1;      // warp grid 2(M) x 4(N)
    int bm = blockIdx.y, bn = blockIdx.x;
    int KC = K >> 6;
    uint32_t sbase = smem_u32(smem);
    uint32_t mb0 = smem_u32(&s_full[0]);

    int blkA = (IMS == 4) ? bm : (bm >> 1);
    int roff = (IMS == 4) ? 0 : ((bm & 1) << 6);

    if (tid == 0) {
#pragma unroll
        for (int s = 0; s < STAGES; ++s) MBAR_INIT(mb0 + s * 8, 1);
    }
    __syncthreads();

    float acc[IMS][4][4];
#pragma unroll
    for (int i = 0; i < IMS; ++i)
#pragma unroll
        for (int j = 0; j < 4; ++j)
#pragma unroll
            for (int q = 0; q < 4; ++q) acc[i][j][q] = 0.f;

    const int la15 = lane & 15, lahi = lane >> 4;
    const int bmx = lane >> 3;
    const int brow_base = wn * 32 + ((bmx >> 1) << 3) + (lane & 7);
    const int bcs = bmx & 1;

    const int nc = KC;

    if (tid == 0) {
#pragma unroll
        for (int c = 0; c < STAGES - 1; ++c) {
            uint32_t m = mb0 + c * 8;
            MBAR_EXPECT_TX(m, SSTRIDE);
            bulk_g2s(sbase + c * SSTRIDE,
                     Apk + (((size_t)(blkA * KC + c)) * 128 + roff) * 128, ABYTES, m);
            bulk_g2s(sbase + c * SSTRIDE + ABYTES,
                     Bpk + ((size_t)bn * KC + c) * 16384, 32768, m);
        }
    }

    for (int c = 0; c < nc; ++c) {
        int s = c % STAGES;
        mbar_wait(mb0 + s * 8, (c / STAGES) & 1);

        if (tid == 0) {
            int cn = c + STAGES - 1;
            if (cn < nc) {
                int sn = cn % STAGES;
                uint32_t m = mb0 + sn * 8;
                MBAR_EXPECT_TX(m, SSTRIDE);
                bulk_g2s(sbase + sn * SSTRIDE,
                         Apk + (((size_t)(blkA * KC + cn)) * 128 + roff) * 128, ABYTES, m);
                bulk_g2s(sbase + sn * SSTRIDE + ABYTES,
                         Bpk + ((size_t)bn * KC + cn) * 16384, 32768, m);
            }
        }

        uint32_t Ab = sbase + s * SSTRIDE;
        uint32_t Bb = Ab + ABYTES;

#pragma unroll
        for (int kh = 0; kh < 4; ++kh) {
            uint32_t af[2][IMS][4];
            uint32_t bf_[2][4][2];
#pragma unroll
            for (int im = 0; im < IMS; ++im) {
                int r = wm * (IMS * 16) + im * 16 + la15;
                int cch = kh * 2 + lahi;
                uint32_t off = (uint32_t)(r * 256 + (((cch ^ (r & 7))) << 4));
                ldsm4(af[0][im], Ab + off);
                ldsm4(af[1][im], Ab + off + 128);
            }
#pragma unroll
            for (int g2 = 0; g2 < 2; ++g2) {
                int nr = brow_base + g2 * 16;
                int cch = kh * 2 + bcs;
                uint32_t off = (uint32_t)(nr * 256 + (((cch ^ (nr & 7))) << 4));
#pragma unroll
                for (int pl = 0; pl < 2; ++pl) {
                    uint32_t t4[4];
                    ldsm4(t4, Bb + off + pl * 128);
                    bf_[pl][g2 * 2][0]     = t4[0];
                    bf_[pl][g2 * 2][1]     = t4[1];
                    bf_[pl][g2 * 2 + 1][0] = t4[2];
                    bf_[pl][g2 * 2 + 1][1] = t4[3];
                }
            }
#pragma unroll
            for (int im = 0; im < IMS; ++im)
#pragma unroll
                for (int in_ = 0; in_ < 4; ++in_) {
                    mma16816(acc[im][in_], af[0][im], bf_[0][in_]);
                    mma16816(acc[im][in_], af[0][im], bf_[1][in_]);
                    mma16816(acc[im][in_], af[1][im], bf_[0][in_]);
                }
        }
        __syncthreads();
    }

    // ---------------- epilogue ----------------
    int r0 = bm * (IMS * 32) + wm * (IMS * 16) + (lane >> 2);
    int c0base = bn * 128 + wn * 32 + 2 * (lane & 3);
    int KCo = N >> 6;

#pragma unroll
    for (int im = 0; im < IMS; ++im) {
#pragma unroll
        for (int half = 0; half < 2; ++half) {
            int row = r0 + im * 16 + half * 8;
#pragma unroll
            for (int in_ = 0; in_ < 4; ++in_) {
                int col = c0base + in_ * 8;
                float v0 = acc[im][in_][half * 2 + 0];
                float v1 = acc[im][in_][half * 2 + 1];
                if (EPI == EPI_NONE) {
                    *(float2*)(outf + (size_t)row * Nl + col) = make_float2(v0, v1);
                } else if (EPI == EPI_RES) {
                    const float* rr = Res + (size_t)row * Nl + col;
                    v0 += bias[col]     + rr[0];
                    v1 += bias[col + 1] + rr[1];
                    *(float2*)(outf + (size_t)row * Nl + col) = make_float2(v0, v1);
                } else if (EPI == EPI_GELU_PK) {
                    v0 += bias[col];
                    v1 += bias[col + 1];
                    v0 = 0.5f * v0 * (1.0f + erff(v0 * 0.7071067811865476f));
                    v1 = 0.5f * v1 * (1.0f + erff(v1 * 0.7071067811865476f));
                    __nv_bfloat16 h0 = __float2bfloat16(v0);
                    __nv_bfloat16 h1 = __float2bfloat16(v1);
                    __nv_bfloat16 l0 = __float2bfloat16(v0 - __bfloat162float(h0));
                    __nv_bfloat16 l1 = __float2bfloat16(v1 - __bfloat162float(h1));
                    int blk = row >> 7, r = row & 127;
                    size_t base = pk_rowseg(KCo, blk, col >> 6, r);
                    int wi = pk_within(r, col & 63);
                    *(__nv_bfloat162*)(outpk + base + wi) =
                        __nv_bfloat162(h0, h1);
                    *(__nv_bfloat162*)(outpk + base + 64 + wi) =
                        __nv_bfloat162(l0, l1);
                }
            }
        }
    }
}

// ======================= LM head GEMM (fp16 2-term: AhB + AlB) =======================
// A: packed fp16 hi/lo (256B rows). B: packed fp16 single plane (128B rows).
#define HEAD_SMEM (STAGES * (32768 + 16384))

__global__ __launch_bounds__(256, 1)
void hgemm_head(const __half* __restrict__ Apk,
                const __half* __restrict__ Bpk,
                const float* __restrict__ bias,
                float* __restrict__ outf,
                int N, int K, int Nl) {
    constexpr int ABYTES = 32768;
    constexpr int BBYTES = 16384;
    constexpr int SSTRIDE = ABYTES + BBYTES;
    extern __shared__ __align__(1024) char smem[];
    __shared__ __align__(8) uint64_t s_full[STAGES];

    int tid = threadIdx.x;
    int lane = tid & 31, w = tid >> 5;
    int wm = w & 1, wn = w >> 1;
    int bm = blockIdx.y, bn = blockIdx.x;
    int KC = K >> 6;
    uint32_t sbase = smem_u32(smem);
    uint32_t mb0 = smem_u32(&s_full[0]);

    if (tid == 0) {
#pragma unroll
        for (int s = 0; s < STAGES; ++s) MBAR_INIT(mb0 + s * 8, 1);
    }
    __syncthreads();

    float acc[4][4][4];
#pragma unroll
    for (int i = 0; i < 4; ++i)
#pragma unroll
        for (int j = 0; j < 4; ++j)
#pragma unroll
            for (int q = 0; q < 4; ++q) acc[i][j][q] = 0.f;

    const int la15 = lane & 15, lahi = lane >> 4;
    const int bmx = lane >> 3;
    const int brow_base = wn * 32 + ((bmx >> 1) << 3) + (lane & 7);
    const int bcs = bmx & 1;

    if (tid == 0) {
#pragma unroll
        for (int c = 0; c < STAGES - 1; ++c) {
            uint32_t m = mb0 + c * 8;
            MBAR_EXPECT_TX(m, SSTRIDE);
            bulk_g2s(sbase + c * SSTRIDE,
                     Apk + ((size_t)bm * KC + c) * 16384, ABYTES, m);
            bulk_g2s(sbase + c * SSTRIDE + ABYTES,
                     Bpk + ((size_t)bn * KC + c) * 8192, BBYTES, m);
        }
    }

    for (int c = 0; c < KC; ++c) {
        int s = c % STAGES;
        mbar_wait(mb0 + s * 8, (c / STAGES) & 1);

        if (tid == 0) {
            int cn = c + STAGES - 1;
            if (cn < KC) {
                int sn = cn % STAGES;
                uint32_t m = mb0 + sn * 8;
                MBAR_EXPECT_TX(m, SSTRIDE);
                bulk_g2s(sbase + sn * SSTRIDE,
                         Apk + ((size_t)bm * KC + cn) * 16384, ABYTES, m);
                bulk_g2s(sbase + sn * SSTRIDE + ABYTES,
                         Bpk + ((size_t)bn * KC + cn) * 8192, BBYTES, m);
            }
        }

        uint32_t Ab = sbase + s * SSTRIDE;
        uint32_t Bb = Ab + ABYTES;

#pragma unroll
        for (int kh = 0; kh < 4; ++kh) {
            uint32_t af[2][4][4];
            uint32_t bf_[4][2];
#pragma unroll
            for (int im = 0; im < 4; ++im) {
                int r = wm * 64 + im * 16 + la15;
                int cch = kh * 2 + lahi;
                uint32_t off = (uint32_t)(r * 256 + (((cch ^ (r & 7))) << 4));
                ldsm4(af[0][im], Ab + off);
                ldsm4(af[1][im], Ab + off + 128);
            }
#pragma unroll
            for (int g2 = 0; g2 < 2; ++g2) {
                int nr = brow_base + g2 * 16;
                int cch = kh * 2 + bcs;
                uint32_t off = (uint32_t)(nr * 128 + (((cch ^ (nr & 7))) << 4));
                uint32_t t4[4];
                ldsm4(t4, Bb + off);
                bf_[g2 * 2][0]     = t4[0];
                bf_[g2 * 2][1]     = t4[1];
                bf_[g2 * 2 + 1][0] = t4[2];
                bf_[g2 * 2 + 1][1] = t4[3];
            }
#pragma unroll
            for (int im = 0; im < 4; ++im)
#pragma unroll
                for (int in_ = 0; in_ < 4; ++in_) {
                    mma16816h(acc[im][in_], af[0][im], bf_[in_]);
                    mma16816h(acc[im][in_], af[1][im], bf_[in_]);
                }
        }
        __syncthreads();
    }

    // epilogue: bias + bounds (N may exceed Nl)
    int r0 = bm * 128 + wm * 64 + (lane >> 2);
    int c0base = bn * 128 + wn * 32 + 2 * (lane & 3);
#pragma unroll
    for (int im = 0; im < 4; ++im) {
#pragma unroll
        for (int half = 0; half < 2; ++half) {
            int row = r0 + im * 16 + half * 8;
#pragma unroll
            for (int in_ = 0; in_ < 4; ++in_) {
                int col = c0base + in_ * 8;
                float v0 = acc[im][in_][half * 2 + 0];
                float v1 = acc[im][in_][half * 2 + 1];
                if (col < Nl)     outf[(size_t)row * Nl + col]     = v0 + bias[col];
                if (col + 1 < Nl) outf[(size_t)row * Nl + col + 1] = v1 + bias[col + 1];
            }
        }
    }
}

// ---------------- tiled causal attention: 64 q-rows per block ----------------
#define ATT_PAD 68
#define ATT_ROW (64 * ATT_PAD)
#define ATT_SMEM (4 * ATT_ROW * 4)

__global__ __launch_bounds__(256)
void attn_kernel(const float* __restrict__ QKV,
                 __nv_bfloat16* __restrict__ Opk) {
    extern __shared__ float asm_[];
    float* sq = asm_;
    float* sk = asm_ + ATT_ROW;
    float* sv = asm_ + 2 * ATT_ROW;
    float* sp = asm_ + 3 * ATT_ROW;

    int tid = threadIdx.x;
    int q0 = blockIdx.x * 64;
    int hh = blockIdx.y;
    int b  = blockIdx.z;
    int qr = tid >> 2, dg = tid & 3;
    int qg = q0 + qr;

    const float scale = rsqrtf((float)CC);

    {
        int r = tid >> 4, c4 = (tid & 15) * 4;
#pragma unroll
        for (int it = 0; it < 4; ++it, r += 16) {
            *(float4*)&sq[r * ATT_PAD + c4] =
                *(const float4*)(QKV + ((size_t)(b * TT + q0 + r)) * NQKV + hh * DD + c4);
        }
    }

    float m = -INFINITY, l = 0.f;
    float acc[16];
#pragma unroll
    for (int i = 0; i < 16; ++i) acc[i] = 0.f;

    for (int j0 = 0; j0 <= q0; j0 += 64) {
        __syncthreads();
        {
            int r = tid >> 4, c4 = (tid & 15) * 4;
#pragma unroll
            for (int it = 0; it < 4; ++it, r += 16) {
                size_t rb = ((size_t)(b * TT + j0 + r)) * NQKV + hh * DD + c4;
                *(float4*)&sk[r * ATT_PAD + c4] = *(const float4*)(QKV + rb + CC);
                *(float4*)&sv[r * ATT_PAD + c4] = *(const float4*)(QKV + rb + 2 * CC);
            }
        }
        __syncthreads();

        float s[16];
#pragma unroll
        for (int jj = 0; jj < 16; ++jj) s[jj] = 0.f;
        const float* qrow = sq + qr * ATT_PAD;
#pragma unroll
        for (int k4 = 0; k4 < 16; ++k4) {
            float4 qv = *(const float4*)(qrow + k4 * 4);
#pragma unroll
            for (int jj = 0; jj < 16; ++jj) {
                int j = jj * 4 + dg;
                float4 kv = *(const float4*)(sk + j * ATT_PAD + k4 * 4);
                s[jj] = fmaf(qv.x, kv.x, s[jj]);
                s[jj] = fmaf(qv.y, kv.y, s[jj]);
                s[jj] = fmaf(qv.z, kv.z, s[jj]);
                s[jj] = fmaf(qv.w, kv.w, s[jj]);
            }
        }

        float tmax = -INFINITY;
#pragma unroll
        for (int jj = 0; jj < 16; ++jj) {
            int j = jj * 4 + dg;
            s[jj] = (j0 + j <= qg) ? s[jj] * scale : -INFINITY;
            tmax = fmaxf(tmax, s[jj]);
        }
        tmax = fmaxf(tmax, __shfl_xor_sync(0xFFFFFFFF, tmax, 1));
        tmax = fmaxf(tmax, __shfl_xor_sync(0xFFFFFFFF, tmax, 2));

        float newm = fmaxf(m, tmax);
        float corr = __expf(m - newm);
        float lp = 0.f;
#pragma unroll
        for (int jj = 0; jj < 16; ++jj) {
            int j = jj * 4 + dg;
            float p = __expf(s[jj] - newm);
            sp[qr * ATT_PAD + j] = p;
            lp += p;
        }
        lp += __shfl_xor_sync(0xFFFFFFFF, lp, 1);
        lp += __shfl_xor_sync(0xFFFFFFFF, lp, 2);
        l = l * corr + lp;
        m = newm;
#pragma unroll
        for (int i = 0; i < 16; ++i) acc[i] *= corr;

        __syncthreads();

        const float* prow = sp + qr * ATT_PAD;
#pragma unroll 8
        for (int j = 0; j < 64; ++j) {
            float pj = prow[j];
            const float* vrow = sv + j * ATT_PAD + dg * 16;
            float4 v0 = *(const float4*)(vrow);
            float4 v1 = *(const float4*)(vrow + 4);
            float4 v2 = *(const float4*)(vrow + 8);
            float4 v3 = *(const float4*)(vrow + 12);
            acc[0]  = fmaf(pj, v0.x, acc[0]);  acc[1]  = fmaf(pj, v0.y, acc[1]);
            acc[2]  = fmaf(pj, v0.z, acc[2]);  acc[3]  = fmaf(pj, v0.w, acc[3]);
            acc[4]  = fmaf(pj, v1.x, acc[4]);  acc[5]  = fmaf(pj, v1.y, acc[5]);
            acc[6]  = fmaf(pj, v1.z, acc[6]);  acc[7]  = fmaf(pj, v1.w, acc[7]);
            acc[8]  = fmaf(pj, v2.x, acc[8]);  acc[9]  = fmaf(pj, v2.y, acc[9]);
            acc[10] = fmaf(pj, v2.z, acc[10]); acc[11] = fmaf(pj, v2.w, acc[11]);
            acc[12] = fmaf(pj, v3.x, acc[12]); acc[13] = fmaf(pj, v3.y, acc[13]);
            acc[14] = fmaf(pj, v3.z, acc[14]); acc[15] = fmaf(pj, v3.w, acc[15]);
        }
    }

    float inv = 1.0f / l;
    int rowg = b * TT + qg;
    int blk = rowg >> 7, r = rowg & 127;
    size_t base = pk_rowseg(12, blk, hh, r);
#pragma unroll
    for (int dd = 0; dd < 16; dd += 2) {
        int d = dg * 16 + dd;
        float v0 = acc[dd] * inv;
        float v1 = acc[dd + 1] * inv;
        __nv_bfloat16 h0 = __float2bfloat16(v0);
        __nv_bfloat16 h1 = __float2bfloat16(v1);
        __nv_bfloat16 l0 = __float2bfloat16(v0 - __bfloat162float(h0));
        __nv_bfloat16 l1 = __float2bfloat16(v1 - __bfloat162float(h1));
        int wi = pk_within(r, d);
        *(__nv_bfloat162*)(Opk + base + wi)      = __nv_bfloat162(h0, h1);
        *(__nv_bfloat162*)(Opk + base + 64 + wi) = __nv_bfloat162(l0, l1);
    }
}

// ======================= launch =======================
extern "C" void kernel_launch(void* const* d_in, const int* in_sizes, int n_in,
                              void* d_out, int out_size) {
    const int*   tokens = (const int*)  d_in[0];
    const float* wte    = (const float*)d_in[1];
    const float* wpe    = (const float*)d_in[2];
    const float* Wq     = (const float*)d_in[3];
    const float* Wk     = (const float*)d_in[4];
    const float* Wv     = (const float*)d_in[5];
    const float* Wo     = (const float*)d_in[6];
    const float* bo     = (const float*)d_in[7];
    const float* ln1g   = (const float*)d_in[8];
    const float* ln1b   = (const float*)d_in[9];
    const float* ln2g   = (const float*)d_in[10];
    const float* ln2b   = (const float*)d_in[11];
    const float* W1     = (const float*)d_in[12];
    const float* b1     = (const float*)d_in[13];
    const float* W2     = (const float*)d_in[14];
    const float* b2     = (const float*)d_in[15];
    const float* lnfg   = (const float*)d_in[16];
    const float* lnfb   = (const float*)d_in[17];
    const float* Wh     = (const float*)d_in[18];
    const float* bh     = (const float*)d_in[19];
    float* out = (float*)d_out;

    static bool attrs_set = false;
    if (!attrs_set) {
        cudaFuncSetAttribute(hgemm<EPI_NONE, 4>,    cudaFuncAttributeMaxDynamicSharedMemorySize, HG_SMEM_128);
        cudaFuncSetAttribute(hgemm<EPI_GELU_PK, 4>, cudaFuncAttributeMaxDynamicSharedMemorySize, HG_SMEM_128);
        cudaFuncSetAttribute(hgemm<EPI_RES, 2>,     cudaFuncAttributeMaxDynamicSharedMemorySize, HG_SMEM_64);
        cudaFuncSetAttribute(hgemm_head,            cudaFuncAttributeMaxDynamicSharedMemorySize, HEAD_SMEM);
        cudaFuncSetAttribute(attn_kernel,           cudaFuncAttributeMaxDynamicSharedMemorySize, ATT_SMEM);
        attrs_set = true;
    }

    float *h, *qkv;
    __nv_bfloat16 *xpk, *opk, *mpk, *wqkvpk, *wopk, *w1pk, *w2pk, *whpk;
    cudaGetSymbolAddress((void**)&h,      g_h);
    cudaGetSymbolAddress((void**)&qkv,    g_qkv);
    cudaGetSymbolAddress((void**)&xpk,    g_xpk);
    cudaGetSymbolAddress((void**)&opk,    g_opk);
    cudaGetSymbolAddress((void**)&mpk,    g_mpk);
    cudaGetSymbolAddress((void**)&wqkvpk, g_wqkvpk);
    cudaGetSymbolAddress((void**)&wopk,   g_wopk);
    cudaGetSymbolAddress((void**)&w1pk,   g_w1pk);
    cudaGetSymbolAddress((void**)&w2pk,   g_w2pk);
    cudaGetSymbolAddress((void**)&whpk,   g_whpk);
    __half* xpk16 = (__half*)xpk;
    __half* whpk16 = (__half*)whpk;

    dim3 gQKV(NQKV / 128, MM / 128);   // (18, 32)
    dim3 gC64(CC / 128, MM / 64);      // (6, 64)  BM=64
    dim3 gF(FF / 128, MM / 128);       // (24, 32)
    dim3 gV(VPAD / 128, MM / 128);     // (393, 32)

    dim3 pCC(12, 12);
    dim3 pW1(48, 12);
    dim3 pW2(12, 48);
    dim3 pWh(786, 12);

    embed_kernel<<<MM, 256>>>(tokens, wte, wpe, h);
    pack_w16_kernel<<<pWh, 256>>>(Wh, whpk16, CC, VV);

    for (int l = 0; l < LL; l++) {
        pack_w_kernel<<<pCC, 256>>>(Wq + (size_t)l * CC * CC, wqkvpk, CC, CC, 0);
        pack_w_kernel<<<pCC, 256>>>(Wk + (size_t)l * CC * CC, wqkvpk, CC, CC, 768);
        pack_w_kernel<<<pCC, 256>>>(Wv + (size_t)l * CC * CC, wqkvpk, CC, CC, 1536);
        pack_w_kernel<<<pCC, 256>>>(Wo + (size_t)l * CC * CC, wopk, CC, CC, 0);
        pack_w_kernel<<<pW1, 256>>>(W1 + (size_t)l * CC * FF, w1pk, CC, FF, 0);
        pack_w_kernel<<<pW2, 256>>>(W2 + (size_t)l * FF * CC, w2pk, FF, CC, 0);

        ln_pk_kernel<<<MM, 256>>>(h, ln1g + l * CC, ln1b + l * CC, xpk);
        hgemm<EPI_NONE, 4><<<gQKV, 256, HG_SMEM_128>>>(xpk, wqkvpk, nullptr, nullptr,
                                                       qkv, nullptr, NQKV, CC, NQKV);

        attn_kernel<<<dim3(TT / 64, HH, BB), 256, ATT_SMEM>>>(qkv, opk);

        hgemm<EPI_RES, 2><<<gC64, 256, HG_SMEM_64>>>(opk, wopk, bo + l * CC, h,
                                                     h, nullptr, CC, CC, CC);

        ln_pk_kernel<<<MM, 256>>>(h, ln2g + l * CC, ln2b + l * CC, xpk);
        hgemm<EPI_GELU_PK, 4><<<gF, 256, HG_SMEM_128>>>(xpk, w1pk, b1 + l * FF, nullptr,
                                                        nullptr, mpk, FF, CC, FF);
        hgemm<EPI_RES, 2><<<gC64, 256, HG_SMEM_64>>>(mpk, w2pk, b2 + l * CC, h,
                                                     h, nullptr, CC, FF, CC);
    }

    ln_pk16_kernel<<<MM, 256>>>(h, lnfg, lnfb, xpk16);
    hgemm_head<<<gV, 256, HEAD_SMEM>>>(xpk16, whpk16, bh, out, VPAD, CC, VV);
}

// round 12
// speedup vs baseline: 1.1948x; 1.0653x over previous
#include <cuda_runtime.h>
#include <cuda_bf16.h>
#include <cuda_fp16.h>
#include <math.h>
#include <stdint.h>

// Problem dims
#define BB 4
#define TT 1024
#define CC 768
#define HH 12
#define LL 6
#define VV 50257
#define DD 64
#define FF 3072
#define MM (BB*TT)        // 4096 rows
#define NQKV 2304
#define VPAD 50304        // 393*128

// ---------------- scratch (device globals; allocation-free) ----------------
__device__ float g_h[(size_t)MM*CC];
__device__ float g_qkv[(size_t)MM*NQKV];
// packed bf16 hi/lo operand buffers: layout [blk128][K/64][r:128][pl:2][64]
__device__ __align__(256) __nv_bfloat16 g_xpk [(size_t)MM*CC*2];   // also fp16 single-plane for head
__device__ __align__(256) __nv_bfloat16 g_opk [(size_t)MM*CC*2];
__device__ __align__(256) __nv_bfloat16 g_mpk [(size_t)MM*FF*2];
__device__ __align__(256) __nv_bfloat16 g_wqkvpk[(size_t)NQKV*CC*2];
__device__ __align__(256) __nv_bfloat16 g_wopk  [(size_t)CC*CC*2];
__device__ __align__(256) __nv_bfloat16 g_w1pk  [(size_t)FF*CC*2];
__device__ __align__(256) __nv_bfloat16 g_w2pk  [(size_t)CC*FF*2];
__device__ __align__(256) __nv_bfloat16 g_whpk  [(size_t)VPAD*CC*2]; // fp16 single plane uses half

// ======================= PTX helpers (sm_90 baseline only) =======================
__device__ __forceinline__ uint32_t smem_u32(const void* p) {
    uint32_t a;
    asm("{ .reg .u64 t; cvta.to.shared.u64 t, %1; cvt.u32.u64 %0, t; }"
        : "=r"(a) : "l"(p));
    return a;
}
#define MBAR_INIT(addr, cnt) \
    asm volatile("mbarrier.init.shared.b64 [%0], %1;" :: "r"(addr), "r"((uint32_t)(cnt)) : "memory")
#define MBAR_EXPECT_TX(addr, bytes) \
    asm volatile("mbarrier.arrive.expect_tx.shared.b64 _, [%0], %1;" \
                 :: "r"(addr), "r"((uint32_t)(bytes)) : "memory")

__device__ __forceinline__ void mbar_wait(uint32_t mbar, uint32_t parity) {
    uint32_t done;
    asm volatile(
        "{\n\t.reg .pred p;\n\t"
        "mbarrier.try_wait.parity.acquire.cta.shared::cta.b64 p, [%1], %2;\n\t"
        "selp.b32 %0, 1, 0, p;\n\t}"
        : "=r"(done) : "r"(mbar), "r"(parity) : "memory");
    if (!done) {
        asm volatile(
            "{\n\t.reg .pred P1;\n\t"
            "WAIT_LOOP_%=:\n\t"
            "mbarrier.try_wait.parity.acquire.cta.shared::cta.b64 P1, [%0], %1, 0x989680;\n\t"
            "@P1 bra.uni WAIT_DONE_%=;\n\t"
            "bra.uni WAIT_LOOP_%=;\n\t"
            "WAIT_DONE_%=:\n\t}"
            :: "r"(mbar), "r"(parity) : "memory");
    }
}
__device__ __forceinline__ void bulk_g2s(uint32_t dst, const void* src,
                                         uint32_t bytes, uint32_t mbar) {
    asm volatile(
        "cp.async.bulk.shared::cluster.global.mbarrier::complete_tx::bytes "
        "[%0], [%1], %2, [%3];"
        :: "r"(dst), "l"(src), "r"(bytes), "r"(mbar) : "memory");
}
__device__ __forceinline__ void ldsm4(uint32_t* r, uint32_t addr) {
    asm volatile("ldmatrix.sync.aligned.m8n8.x4.shared.b16 {%0,%1,%2,%3}, [%4];"
        : "=r"(r[0]), "=r"(r[1]), "=r"(r[2]), "=r"(r[3]) : "r"(addr));
}
__device__ __forceinline__ void mma16816(float* d, const uint32_t* a, const uint32_t* b) {
    asm volatile(
        "mma.sync.aligned.m16n8k16.row.col.f32.bf16.bf16.f32 "
        "{%0,%1,%2,%3}, {%4,%5,%6,%7}, {%8,%9}, {%0,%1,%2,%3};"
        : "+f"(d[0]), "+f"(d[1]), "+f"(d[2]), "+f"(d[3])
        : "r"(a[0]), "r"(a[1]), "r"(a[2]), "r"(a[3]), "r"(b[0]), "r"(b[1]));
}
__device__ __forceinline__ void mma16816h(float* d, const uint32_t* a, const uint32_t* b) {
    asm volatile(
        "mma.sync.aligned.m16n8k16.row.col.f32.f16.f16.f32 "
        "{%0,%1,%2,%3}, {%4,%5,%6,%7}, {%8,%9}, {%0,%1,%2,%3};"
        : "+f"(d[0]), "+f"(d[1]), "+f"(d[2]), "+f"(d[3])
        : "r"(a[0]), "r"(a[1]), "r"(a[2]), "r"(a[3]), "r"(b[0]), "r"(b[1]));
}

// packed layout helper: element index for (blk128, kc, r, pl, kk)
__device__ __forceinline__ size_t pk_rowseg(int KC, int blk, int kc, int r) {
    return ((size_t)(blk * KC + kc) * 128 + r) * 128;
}
__device__ __forceinline__ int pk_within(int r, int kk) {
    int ch = kk >> 3, w8 = kk & 7;
    return ((ch ^ (r & 7)) << 3) + w8;
}

// ======================= small kernels =======================
__global__ void embed_kernel(const int* __restrict__ tok,
                             const float* __restrict__ wte,
                             const float* __restrict__ wpe,
                             float* __restrict__ h) {
    int bt = blockIdx.x;
    int t  = bt % TT;
    int tk = tok[bt];
    const float* we = wte + (size_t)tk * CC;
    const float* wp = wpe + (size_t)t  * CC;
    float* hr = h + (size_t)bt * CC;
    for (int c = threadIdx.x; c < CC; c += blockDim.x)
        hr[c] = we[c] + wp[c];
}

// LayerNorm producing packed bf16 hi/lo A-operand (KC = CC/64 = 12)
__global__ void ln_pk_kernel(const float* __restrict__ x,
                             const float* __restrict__ gamma,
                             const float* __restrict__ beta,
                             __nv_bfloat16* __restrict__ outpk) {
    int row = blockIdx.x;
    const float* xr = x + (size_t)row * CC;
    __shared__ float red[256];
    int tid = threadIdx.x;

    float s = 0.f;
    for (int c = tid; c < CC; c += 256) s += xr[c];
    red[tid] = s; __syncthreads();
    for (int o = 128; o > 0; o >>= 1) {
        if (tid < o) red[tid] += red[tid + o];
        __syncthreads();
    }
    float mu = red[0] * (1.0f / CC);
    __syncthreads();

    float v = 0.f;
    for (int c = tid; c < CC; c += 256) { float d = xr[c] - mu; v += d * d; }
    red[tid] = v; __syncthreads();
    for (int o = 128; o > 0; o >>= 1) {
        if (tid < o) red[tid] += red[tid + o];
        __syncthreads();
    }
    float rstd = rsqrtf(red[0] * (1.0f / CC) + 1e-5f);

    int blk = row >> 7, r = row & 127;
    for (int c = tid; c < CC; c += 256) {
        float val = (xr[c] - mu) * rstd * gamma[c] + beta[c];
        __nv_bfloat16 hi = __float2bfloat16(val);
        __nv_bfloat16 lo = __float2bfloat16(val - __bfloat162float(hi));
        size_t base = pk_rowseg(12, blk, c >> 6, r);
        int w = pk_within(r, c & 63);
        outpk[base + w]      = hi;
        outpk[base + 64 + w] = lo;
    }
}

// LayerNorm producing packed fp16 SINGLE-plane A-operand (for LM head)
// rowseg = 64 halfs: base = ((blk*12 + kc)*128 + r)*64
__global__ void ln_pk16_kernel(const float* __restrict__ x,
                               const float* __restrict__ gamma,
                               const float* __restrict__ beta,
                               __half* __restrict__ outpk) {
    int row = blockIdx.x;
    const float* xr = x + (size_t)row * CC;
    __shared__ float red[256];
    int tid = threadIdx.x;

    float s = 0.f;
    for (int c = tid; c < CC; c += 256) s += xr[c];
    red[tid] = s; __syncthreads();
    for (int o = 128; o > 0; o >>= 1) {
        if (tid < o) red[tid] += red[tid + o];
        __syncthreads();
    }
    float mu = red[0] * (1.0f / CC);
    __syncthreads();

    float v = 0.f;
    for (int c = tid; c < CC; c += 256) { float d = xr[c] - mu; v += d * d; }
    red[tid] = v; __syncthreads();
    for (int o = 128; o > 0; o >>= 1) {
        if (tid < o) red[tid] += red[tid + o];
        __syncthreads();
    }
    float rstd = rsqrtf(red[0] * (1.0f / CC) + 1e-5f);

    int blk = row >> 7, r = row & 127;
    for (int c = tid; c < CC; c += 256) {
        float val = (xr[c] - mu) * rstd * gamma[c] + beta[c];
        size_t base = ((size_t)(blk * 12 + (c >> 6)) * 128 + r) * 64;
        int w = pk_within(r, c & 63);
        outpk[base + w] = __float2half_rn(val);
    }
}

// transpose + convert + split weight W[K,N](fp32) -> packed bf16 hi/lo layout
__global__ __launch_bounds__(256)
void pack_w_kernel(const float* __restrict__ W, __nv_bfloat16* __restrict__ Bpk,
                   int K, int N, int n0out) {
    __shared__ float sm[64][65];
    int tid = threadIdx.x;
    int n0 = blockIdx.x * 64;
    int k0 = blockIdx.y * 64;
    int KC = K >> 6;

    for (int idx = tid; idx < 64 * 64; idx += 256) {
        int kr = idx >> 6, nc = idx & 63;
        int gn = n0 + nc;
        sm[kr][nc] = (gn < N) ? W[(size_t)(k0 + kr) * N + gn] : 0.f;
    }
    __syncthreads();

    for (int g = tid; g < 512; g += 256) {
        int n = g >> 3, ch = g & 7;
        int gn = n0out + n0 + n;
        int bn = gn >> 7, r = gn & 127;
        size_t base = pk_rowseg(KC, bn, blockIdx.y, r);
        int w = (ch ^ (r & 7)) << 3;
        union { uint4 v; __nv_bfloat16 b[8]; } uh, ul;
#pragma unroll
        for (int j = 0; j < 8; ++j) {
            float x = sm[ch * 8 + j][n];
            __nv_bfloat16 hi = __float2bfloat16(x);
            uh.b[j] = hi;
            ul.b[j] = __float2bfloat16(x - __bfloat162float(hi));
        }
        *(uint4*)(Bpk + base + w)      = uh.v;
        *(uint4*)(Bpk + base + 64 + w) = ul.v;
    }
}

// transpose + convert weight W[K,N](fp32) -> packed fp16 SINGLE-plane layout
__global__ __launch_bounds__(256)
void pack_w16_kernel(const float* __restrict__ W, __half* __restrict__ Bpk,
                     int K, int N) {
    __shared__ float sm[64][65];
    int tid = threadIdx.x;
    int n0 = blockIdx.x * 64;
    int k0 = blockIdx.y * 64;
    int KC = K >> 6;

    for (int idx = tid; idx < 64 * 64; idx += 256) {
        int kr = idx >> 6, nc = idx & 63;
        int gn = n0 + nc;
        sm[kr][nc] = (gn < N) ? W[(size_t)(k0 + kr) * N + gn] : 0.f;
    }
    __syncthreads();

    for (int g = tid; g < 512; g += 256) {
        int n = g >> 3, ch = g & 7;
        int gn = n0 + n;
        int bn = gn >> 7, r = gn & 127;
        size_t base = ((size_t)(bn * KC + blockIdx.y) * 128 + r) * 64;
        int w = (ch ^ (r & 7)) << 3;
        union { uint4 v; __half b[8]; } uh;
#pragma unroll
        for (int j = 0; j < 8; ++j)
            uh.b[j] = __float2half_rn(sm[ch * 8 + j][n]);
        *(uint4*)(Bpk + base + w) = uh.v;
    }
}

// ======================= HMMA GEMM (mma.sync bf16 x3 split) =======================
#define EPI_NONE 0
#define EPI_BIAS 1
#define EPI_GELU_PK 2
#define EPI_RES 3

#define STAGES 3
#define HG_SMEM_128 (STAGES * (32768 + 32768))
#define HG_SMEM_64  (STAGES * (16384 + 32768))

template<int EPI, int IMS>
__global__ __launch_bounds__(256, 1)
void hgemm(const __nv_bfloat16* __restrict__ Apk,
           const __nv_bfloat16* __restrict__ Bpk,
           const float* __restrict__ bias,
           const float* __restrict__ Res,
           float* __restrict__ outf,
           __nv_bfloat16* __restrict__ outpk,
           int N, int K, int Nl) {
    constexpr int ABYTES = IMS * 8192;
    constexpr int SSTRIDE = ABYTES + 32768;
    extern __shared__ __align__(1024) char smem[];
    __shared__ __align__(8) uint64_t s_full[STAGES];

    int tid = threadIdx.x;
    int lane = tid & 31, w = tid >> 5;
    int wm = w & 1, wn = w >> 1;      // warp grid 2(M) x 4(N)
    int bm = blockIdx.y, bn = blockIdx.x;
    int KC = K >> 6;
    uint32_t sbase = smem_u32(smem);
    uint32_t mb0 = smem_u32(&s_full[0]);

    int blkA = (IMS == 4) ? bm : (bm >> 1);
    int roff = (IMS == 4) ? 0 : ((bm & 1) << 6);

    if (tid == 0) {
#pragma unroll
        for (int s = 0; s < STAGES; ++s) MBAR_INIT(mb0 + s * 8, 1);
    }
    __syncthreads();

    float acc[IMS][4][4];
#pragma unroll
    for (int i = 0; i < IMS; ++i)
#pragma unroll
        for (int j = 0; j < 4; ++j)
#pragma unroll
            for (int q = 0; q < 4; ++q) acc[i][j][q] = 0.f;

    const int la15 = lane & 15, lahi = lane >> 4;
    const int bmx = lane >> 3;
    const int brow_base = wn * 32 + ((bmx >> 1) << 3) + (lane & 7);
    const int bcs = bmx & 1;

    const int nc = KC;

    if (tid == 0) {
#pragma unroll
        for (int c = 0; c < STAGES - 1; ++c) {
            uint32_t m = mb0 + c * 8;
            MBAR_EXPECT_TX(m, SSTRIDE);
            bulk_g2s(sbase + c * SSTRIDE,
                     Apk + (((size_t)(blkA * KC + c)) * 128 + roff) * 128, ABYTES, m);
            bulk_g2s(sbase + c * SSTRIDE + ABYTES,
                     Bpk + ((size_t)bn * KC + c) * 16384, 32768, m);
        }
    }

    for (int c = 0; c < nc; ++c) {
        int s = c % STAGES;
        mbar_wait(mb0 + s * 8, (c / STAGES) & 1);

        if (tid == 0) {
            int cn = c + STAGES - 1;
            if (cn < nc) {
                int sn = cn % STAGES;
                uint32_t m = mb0 + sn * 8;
                MBAR_EXPECT_TX(m, SSTRIDE);
                bulk_g2s(sbase + sn * SSTRIDE,
                         Apk + (((size_t)(blkA * KC + cn)) * 128 + roff) * 128, ABYTES, m);
                bulk_g2s(sbase + sn * SSTRIDE + ABYTES,
                         Bpk + ((size_t)bn * KC + cn) * 16384, 32768, m);
            }
        }

        uint32_t Ab = sbase + s * SSTRIDE;
        uint32_t Bb = Ab + ABYTES;

#pragma unroll
        for (int kh = 0; kh < 4; ++kh) {
            uint32_t af[2][IMS][4];
            uint32_t bf_[2][4][2];
#pragma unroll
            for (int im = 0; im < IMS; ++im) {
                int r = wm * (IMS * 16) + im * 16 + la15;
                int cch = kh * 2 + lahi;
                uint32_t off = (uint32_t)(r * 256 + (((cch ^ (r & 7))) << 4));
                ldsm4(af[0][im], Ab + off);
                ldsm4(af[1][im], Ab + off + 128);
            }
#pragma unroll
            for (int g2 = 0; g2 < 2; ++g2) {
                int nr = brow_base + g2 * 16;
                int cch = kh * 2 + bcs;
                uint32_t off = (uint32_t)(nr * 256 + (((cch ^ (nr & 7))) << 4));
#pragma unroll
                for (int pl = 0; pl < 2; ++pl) {
                    uint32_t t4[4];
                    ldsm4(t4, Bb + off + pl * 128);
                    bf_[pl][g2 * 2][0]     = t4[0];
                    bf_[pl][g2 * 2][1]     = t4[1];
                    bf_[pl][g2 * 2 + 1][0] = t4[2];
                    bf_[pl][g2 * 2 + 1][1] = t4[3];
                }
            }
#pragma unroll
            for (int im = 0; im < IMS; ++im)
#pragma unroll
                for (int in_ = 0; in_ < 4; ++in_) {
                    mma16816(acc[im][in_], af[0][im], bf_[0][in_]);
                    mma16816(acc[im][in_], af[0][im], bf_[1][in_]);
                    mma16816(acc[im][in_], af[1][im], bf_[0][in_]);
                }
        }
        __syncthreads();
    }

    // ---------------- epilogue ----------------
    int r0 = bm * (IMS * 32) + wm * (IMS * 16) + (lane >> 2);
    int c0base = bn * 128 + wn * 32 + 2 * (lane & 3);
    int KCo = N >> 6;

#pragma unroll
    for (int im = 0; im < IMS; ++im) {
#pragma unroll
        for (int half = 0; half < 2; ++half) {
            int row = r0 + im * 16 + half * 8;
#pragma unroll
            for (int in_ = 0; in_ < 4; ++in_) {
                int col = c0base + in_ * 8;
                float v0 = acc[im][in_][half * 2 + 0];
                float v1 = acc[im][in_][half * 2 + 1];
                if (EPI == EPI_NONE) {
                    *(float2*)(outf + (size_t)row * Nl + col) = make_float2(v0, v1);
                } else if (EPI == EPI_RES) {
                    const float* rr = Res + (size_t)row * Nl + col;
                    v0 += bias[col]     + rr[0];
                    v1 += bias[col + 1] + rr[1];
                    *(float2*)(outf + (size_t)row * Nl + col) = make_float2(v0, v1);
                } else if (EPI == EPI_GELU_PK) {
                    v0 += bias[col];
                    v1 += bias[col + 1];
                    v0 = 0.5f * v0 * (1.0f + erff(v0 * 0.7071067811865476f));
                    v1 = 0.5f * v1 * (1.0f + erff(v1 * 0.7071067811865476f));
                    __nv_bfloat16 h0 = __float2bfloat16(v0);
                    __nv_bfloat16 h1 = __float2bfloat16(v1);
                    __nv_bfloat16 l0 = __float2bfloat16(v0 - __bfloat162float(h0));
                    __nv_bfloat16 l1 = __float2bfloat16(v1 - __bfloat162float(h1));
                    int blk = row >> 7, r = row & 127;
                    size_t base = pk_rowseg(KCo, blk, col >> 6, r);
                    int wi = pk_within(r, col & 63);
                    *(__nv_bfloat162*)(outpk + base + wi) =
                        __nv_bfloat162(h0, h1);
                    *(__nv_bfloat162*)(outpk + base + 64 + wi) =
                        __nv_bfloat162(l0, l1);
                }
            }
        }
    }
}

// ======================= LM head GEMM (single-pass fp16) =======================
// A: packed fp16 single plane (128B rows). B: packed fp16 single plane (128B rows).
#define HEAD_SMEM (STAGES * (16384 + 16384))

__global__ __launch_bounds__(256, 1)
void hgemm_head(const __half* __restrict__ Apk,
                const __half* __restrict__ Bpk,
                const float* __restrict__ bias,
                float* __restrict__ outf,
                int N, int K, int Nl) {
    constexpr int ABYTES = 16384;
    constexpr int BBYTES = 16384;
    constexpr int SSTRIDE = ABYTES + BBYTES;
    extern __shared__ __align__(1024) char smem[];
    __shared__ __align__(8) uint64_t s_full[STAGES];

    int tid = threadIdx.x;
    int lane = tid & 31, w = tid >> 5;
    int wm = w & 1, wn = w >> 1;
    int bm = blockIdx.y, bn = blockIdx.x;
    int KC = K >> 6;
    uint32_t sbase = smem_u32(smem);
    uint32_t mb0 = smem_u32(&s_full[0]);

    if (tid == 0) {
#pragma unroll
        for (int s = 0; s < STAGES; ++s) MBAR_INIT(mb0 + s * 8, 1);
    }
    __syncthreads();

    float acc[4][4][4];
#pragma unroll
    for (int i = 0; i < 4; ++i)
#pragma unroll
        for (int j = 0; j < 4; ++j)
#pragma unroll
            for (int q = 0; q < 4; ++q) acc[i][j][q] = 0.f;

    const int la15 = lane & 15, lahi = lane >> 4;
    const int bmx = lane >> 3;
    const int brow_base = wn * 32 + ((bmx >> 1) << 3) + (lane & 7);
    const int bcs = bmx & 1;

    if (tid == 0) {
#pragma unroll
        for (int c = 0; c < STAGES - 1; ++c) {
            uint32_t m = mb0 + c * 8;
            MBAR_EXPECT_TX(m, SSTRIDE);
            bulk_g2s(sbase + c * SSTRIDE,
                     Apk + ((size_t)bm * KC + c) * 8192, ABYTES, m);
            bulk_g2s(sbase + c * SSTRIDE + ABYTES,
                     Bpk + ((size_t)bn * KC + c) * 8192, BBYTES, m);
        }
    }

    for (int c = 0; c < KC; ++c) {
        int s = c % STAGES;
        mbar_wait(mb0 + s * 8, (c / STAGES) & 1);

        if (tid == 0) {
            int cn = c + STAGES - 1;
            if (cn < KC) {
                int sn = cn % STAGES;
                uint32_t m = mb0 + sn * 8;
                MBAR_EXPECT_TX(m, SSTRIDE);
                bulk_g2s(sbase + sn * SSTRIDE,
                         Apk + ((size_t)bm * KC + cn) * 8192, ABYTES, m);
                bulk_g2s(sbase + sn * SSTRIDE + ABYTES,
                         Bpk + ((size_t)bn * KC + cn) * 8192, BBYTES, m);
            }
        }

        uint32_t Ab = sbase + s * SSTRIDE;
        uint32_t Bb = Ab + ABYTES;

#pragma unroll
        for (int kh = 0; kh < 4; ++kh) {
            uint32_t af[4][4];
            uint32_t bf_[4][2];
#pragma unroll
            for (int im = 0; im < 4; ++im) {
                int r = wm * 64 + im * 16 + la15;
                int cch = kh * 2 + lahi;
                uint32_t off = (uint32_t)(r * 128 + (((cch ^ (r & 7))) << 4));
                ldsm4(af[im], Ab + off);
            }
#pragma unroll
            for (int g2 = 0; g2 < 2; ++g2) {
                int nr = brow_base + g2 * 16;
                int cch = kh * 2 + bcs;
                uint32_t off = (uint32_t)(nr * 128 + (((cch ^ (nr & 7))) << 4));
                uint32_t t4[4];
                ldsm4(t4, Bb + off);
                bf_[g2 * 2][0]     = t4[0];
                bf_[g2 * 2][1]     = t4[1];
                bf_[g2 * 2 + 1][0] = t4[2];
                bf_[g2 * 2 + 1][1] = t4[3];
            }
#pragma unroll
            for (int im = 0; im < 4; ++im)
#pragma unroll
                for (int in_ = 0; in_ < 4; ++in_)
                    mma16816h(acc[im][in_], af[im], bf_[in_]);
        }
        __syncthreads();
    }

    // epilogue: bias + bounds (N may exceed Nl)
    int r0 = bm * 128 + wm * 64 + (lane >> 2);
    int c0base = bn * 128 + wn * 32 + 2 * (lane & 3);
#pragma unroll
    for (int im = 0; im < 4; ++im) {
#pragma unroll
        for (int half = 0; half < 2; ++half) {
            int row = r0 + im * 16 + half * 8;
#pragma unroll
            for (int in_ = 0; in_ < 4; ++in_) {
                int col = c0base + in_ * 8;
                float v0 = acc[im][in_][half * 2 + 0];
                float v1 = acc[im][in_][half * 2 + 1];
                if (col < Nl)     outf[(size_t)row * Nl + col]     = v0 + bias[col];
                if (col + 1 < Nl) outf[(size_t)row * Nl + col + 1] = v1 + bias[col + 1];
            }
        }
    }
}

// ---------------- tiled causal attention: 64 q-rows per block ----------------
#define ATT_PAD 68
#define ATT_ROW (64 * ATT_PAD)
#define ATT_SMEM (4 * ATT_ROW * 4)

__global__ __launch_bounds__(256)
void attn_kernel(const float* __restrict__ QKV,
                 __nv_bfloat16* __restrict__ Opk) {
    extern __shared__ float asm_[];
    float* sq = asm_;
    float* sk = asm_ + ATT_ROW;
    float* sv = asm_ + 2 * ATT_ROW;
    float* sp = asm_ + 3 * ATT_ROW;

    int tid = threadIdx.x;
    int q0 = blockIdx.x * 64;
    int hh = blockIdx.y;
    int b  = blockIdx.z;
    int qr = tid >> 2, dg = tid & 3;
    int qg = q0 + qr;

    const float scale = rsqrtf((float)CC);

    {
        int r = tid >> 4, c4 = (tid & 15) * 4;
#pragma unroll
        for (int it = 0; it < 4; ++it, r += 16) {
            *(float4*)&sq[r * ATT_PAD + c4] =
                *(const float4*)(QKV + ((size_t)(b * TT + q0 + r)) * NQKV + hh * DD + c4);
        }
    }

    float m = -INFINITY, l = 0.f;
    float acc[16];
#pragma unroll
    for (int i = 0; i < 16; ++i) acc[i] = 0.f;

    for (int j0 = 0; j0 <= q0; j0 += 64) {
        __syncthreads();
        {
            int r = tid >> 4, c4 = (tid & 15) * 4;
#pragma unroll
            for (int it = 0; it < 4; ++it, r += 16) {
                size_t rb = ((size_t)(b * TT + j0 + r)) * NQKV + hh * DD + c4;
                *(float4*)&sk[r * ATT_PAD + c4] = *(const float4*)(QKV + rb + CC);
                *(float4*)&sv[r * ATT_PAD + c4] = *(const float4*)(QKV + rb + 2 * CC);
            }
        }
        __syncthreads();

        float s[16];
#pragma unroll
        for (int jj = 0; jj < 16; ++jj) s[jj] = 0.f;
        const float* qrow = sq + qr * ATT_PAD;
#pragma unroll
        for (int k4 = 0; k4 < 16; ++k4) {
            float4 qv = *(const float4*)(qrow + k4 * 4);
#pragma unroll
            for (int jj = 0; jj < 16; ++jj) {
                int j = jj * 4 + dg;
                float4 kv = *(const float4*)(sk + j * ATT_PAD + k4 * 4);
                s[jj] = fmaf(qv.x, kv.x, s[jj]);
                s[jj] = fmaf(qv.y, kv.y, s[jj]);
                s[jj] = fmaf(qv.z, kv.z, s[jj]);
                s[jj] = fmaf(qv.w, kv.w, s[jj]);
            }
        }

        float tmax = -INFINITY;
#pragma unroll
        for (int jj = 0; jj < 16; ++jj) {
            int j = jj * 4 + dg;
            s[jj] = (j0 + j <= qg) ? s[jj] * scale : -INFINITY;
            tmax = fmaxf(tmax, s[jj]);
        }
        tmax = fmaxf(tmax, __shfl_xor_sync(0xFFFFFFFF, tmax, 1));
        tmax = fmaxf(tmax, __shfl_xor_sync(0xFFFFFFFF, tmax, 2));

        float newm = fmaxf(m, tmax);
        float corr = __expf(m - newm);
        float lp = 0.f;
#pragma unroll
        for (int jj = 0; jj < 16; ++jj) {
            int j = jj * 4 + dg;
            float p = __expf(s[jj] - newm);
            sp[qr * ATT_PAD + j] = p;
            lp += p;
        }
        lp += __shfl_xor_sync(0xFFFFFFFF, lp, 1);
        lp += __shfl_xor_sync(0xFFFFFFFF, lp, 2);
        l = l * corr + lp;
        m = newm;
#pragma unroll
        for (int i = 0; i < 16; ++i) acc[i] *= corr;

        __syncthreads();

        const float* prow = sp + qr * ATT_PAD;
#pragma unroll 8
        for (int j = 0; j < 64; ++j) {
            float pj = prow[j];
            const float* vrow = sv + j * ATT_PAD + dg * 16;
            float4 v0 = *(const float4*)(vrow);
            float4 v1 = *(const float4*)(vrow + 4);
            float4 v2 = *(const float4*)(vrow + 8);
            float4 v3 = *(const float4*)(vrow + 12);
            acc[0]  = fmaf(pj, v0.x, acc[0]);  acc[1]  = fmaf(pj, v0.y, acc[1]);
            acc[2]  = fmaf(pj, v0.z, acc[2]);  acc[3]  = fmaf(pj, v0.w, acc[3]);
            acc[4]  = fmaf(pj, v1.x, acc[4]);  acc[5]  = fmaf(pj, v1.y, acc[5]);
            acc[6]  = fmaf(pj, v1.z, acc[6]);  acc[7]  = fmaf(pj, v1.w, acc[7]);
            acc[8]  = fmaf(pj, v2.x, acc[8]);  acc[9]  = fmaf(pj, v2.y, acc[9]);
            acc[10] = fmaf(pj, v2.z, acc[10]); acc[11] = fmaf(pj, v2.w, acc[11]);
            acc[12] = fmaf(pj, v3.x, acc[12]); acc[13] = fmaf(pj, v3.y, acc[13]);
            acc[14] = fmaf(pj, v3.z, acc[14]); acc[15] = fmaf(pj, v3.w, acc[15]);
        }
    }

    float inv = 1.0f / l;
    int rowg = b * TT + qg;
    int blk = rowg >> 7, r = rowg & 127;
    size_t base = pk_rowseg(12, blk, hh, r);
#pragma unroll
    for (int dd = 0; dd < 16; dd += 2) {
        int d = dg * 16 + dd;
        float v0 = acc[dd] * inv;
        float v1 = acc[dd + 1] * inv;
        __nv_bfloat16 h0 = __float2bfloat16(v0);
        __nv_bfloat16 h1 = __float2bfloat16(v1);
        __nv_bfloat16 l0 = __float2bfloat16(v0 - __bfloat162float(h0));
        __nv_bfloat16 l1 = __float2bfloat16(v1 - __bfloat162float(h1));
        int wi = pk_within(r, d);
        *(__nv_bfloat162*)(Opk + base + wi)      = __nv_bfloat162(h0, h1);
        *(__nv_bfloat162*)(Opk + base + 64 + wi) = __nv_bfloat162(l0, l1);
    }
}

// ======================= launch =======================
extern "C" void kernel_launch(void* const* d_in, const int* in_sizes, int n_in,
                              void* d_out, int out_size) {
    const int*   tokens = (const int*)  d_in[0];
    const float* wte    = (const float*)d_in[1];
    const float* wpe    = (const float*)d_in[2];
    const float* Wq     = (const float*)d_in[3];
    const float* Wk     = (const float*)d_in[4];
    const float* Wv     = (const float*)d_in[5];
    const float* Wo     = (const float*)d_in[6];
    const float* bo     = (const float*)d_in[7];
    const float* ln1g   = (const float*)d_in[8];
    const float* ln1b   = (const float*)d_in[9];
    const float* ln2g   = (const float*)d_in[10];
    const float* ln2b   = (const float*)d_in[11];
    const float* W1     = (const float*)d_in[12];
    const float* b1     = (const float*)d_in[13];
    const float* W2     = (const float*)d_in[14];
    const float* b2     = (const float*)d_in[15];
    const float* lnfg   = (const float*)d_in[16];
    const float* lnfb   = (const float*)d_in[17];
    const float* Wh     = (const float*)d_in[18];
    const float* bh     = (const float*)d_in[19];
    float* out = (float*)d_out;

    static bool attrs_set = false;
    if (!attrs_set) {
        cudaFuncSetAttribute(hgemm<EPI_NONE, 4>,    cudaFuncAttributeMaxDynamicSharedMemorySize, HG_SMEM_128);
        cudaFuncSetAttribute(hgemm<EPI_GELU_PK, 4>, cudaFuncAttributeMaxDynamicSharedMemorySize, HG_SMEM_128);
        cudaFuncSetAttribute(hgemm<EPI_RES, 2>,     cudaFuncAttributeMaxDynamicSharedMemorySize, HG_SMEM_64);
        cudaFuncSetAttribute(hgemm_head,            cudaFuncAttributeMaxDynamicSharedMemorySize, HEAD_SMEM);
        cudaFuncSetAttribute(attn_kernel,           cudaFuncAttributeMaxDynamicSharedMemorySize, ATT_SMEM);
        attrs_set = true;
    }

    float *h, *qkv;
    __nv_bfloat16 *xpk, *opk, *mpk, *wqkvpk, *wopk, *w1pk, *w2pk, *whpk;
    cudaGetSymbolAddress((void**)&h,      g_h);
    cudaGetSymbolAddress((void**)&qkv,    g_qkv);
    cudaGetSymbolAddress((void**)&xpk,    g_xpk);
    cudaGetSymbolAddress((void**)&opk,    g_opk);
    cudaGetSymbolAddress((void**)&mpk,    g_mpk);
    cudaGetSymbolAddress((void**)&wqkvpk, g_wqkvpk);
    cudaGetSymbolAddress((void**)&wopk,   g_wopk);
    cudaGetSymbolAddress((void**)&w1pk,   g_w1pk);
    cudaGetSymbolAddress((void**)&w2pk,   g_w2pk);
    cudaGetSymbolAddress((void**)&whpk,   g_whpk);
    __half* xpk16 = (__half*)xpk;
    __half* whpk16 = (__half*)whpk;

    dim3 gQKV(NQKV / 128, MM / 128);   // (18, 32)
    dim3 gC64(CC / 128, MM / 64);      // (6, 64)  BM=64
    dim3 gF(FF / 128, MM / 128);       // (24, 32)
    dim3 gV(VPAD / 128, MM / 128);     // (393, 32)

    dim3 pCC(12, 12);
    dim3 pW1(48, 12);
    dim3 pW2(12, 48);
    dim3 pWh(786, 12);

    embed_kernel<<<MM, 256>>>(tokens, wte, wpe, h);
    pack_w16_kernel<<<pWh, 256>>>(Wh, whpk16, CC, VV);

    for (int l = 0; l < LL; l++) {
        pack_w_kernel<<<pCC, 256>>>(Wq + (size_t)l * CC * CC, wqkvpk, CC, CC, 0);
        pack_w_kernel<<<pCC, 256>>>(Wk + (size_t)l * CC * CC, wqkvpk, CC, CC, 768);
        pack_w_kernel<<<pCC, 256>>>(Wv + (size_t)l * CC * CC, wqkvpk, CC, CC, 1536);
        pack_w_kernel<<<pCC, 256>>>(Wo + (size_t)l * CC * CC, wopk, CC, CC, 0);
        pack_w_kernel<<<pW1, 256>>>(W1 + (size_t)l * CC * FF, w1pk, CC, FF, 0);
        pack_w_kernel<<<pW2, 256>>>(W2 + (size_t)l * FF * CC, w2pk, FF, CC, 0);

        ln_pk_kernel<<<MM, 256>>>(h, ln1g + l * CC, ln1b + l * CC, xpk);
        hgemm<EPI_NONE, 4><<<gQKV, 256, HG_SMEM_128>>>(xpk, wqkvpk, nullptr, nullptr,
                                                       qkv, nullptr, NQKV, CC, NQKV);

        attn_kernel<<<dim3(TT / 64, HH, BB), 256, ATT_SMEM>>>(qkv, opk);

        hgemm<EPI_RES, 2><<<gC64, 256, HG_SMEM_64>>>(opk, wopk, bo + l * CC, h,
                                                     h, nullptr, CC, CC, CC);

        ln_pk_kernel<<<MM, 256>>>(h, ln2g + l * CC, ln2b + l * CC, xpk);
        hgemm<EPI_GELU_PK, 4><<<gF, 256, HG_SMEM_128>>>(xpk, w1pk, b1 + l * FF, nullptr,
                                                        nullptr, mpk, FF, CC, FF);
        hgemm<EPI_RES, 2><<<gC64, 256, HG_SMEM_64>>>(mpk, w2pk, b2 + l * CC, h,
                                                     h, nullptr, CC, FF, CC);
    }

    ln_pk16_kernel<<<MM, 256>>>(h, lnfg, lnfb, xpk16);
    hgemm_head<<<gV, 256, HEAD_SMEM>>>(xpk16, whpk16, bh, out, VPAD, CC, VV);
}

// round 13
// speedup vs baseline: 1.3014x; 1.0892x over previous
#include <cuda_runtime.h>
#include <cuda_bf16.h>
#include <cuda_fp16.h>
#include <math.h>
#include <stdint.h>

// Problem dims
#define BB 4
#define TT 1024
#define CC 768
#define HH 12
#define LL 6
#define VV 50257
#define DD 64
#define FF 3072
#define MM (BB*TT)        // 4096 rows
#define NQKV 2304
#define VPAD 50304        // 393*128

// ---------------- scratch (device globals; allocation-free) ----------------
__device__ float g_h[(size_t)MM*CC];
__device__ float g_qkv[(size_t)MM*NQKV];
// packed fp16 operand buffers
// 2-plane (hi/lo) activations: [blk128][K/64][r:128][pl:2][64] halfs
__device__ __align__(256) __half g_xpk [(size_t)MM*CC*2];   // also 1-plane for head
__device__ __align__(256) __half g_opk [(size_t)MM*CC*2];
__device__ __align__(256) __half g_mpk [(size_t)MM*FF*2];
// 1-plane weights: [blkN128][K/64][r:128][64] halfs
__device__ __align__(256) __half g_wqkvpk[(size_t)NQKV*CC];
__device__ __align__(256) __half g_wopk  [(size_t)CC*CC];
__device__ __align__(256) __half g_w1pk  [(size_t)FF*CC];
__device__ __align__(256) __half g_w2pk  [(size_t)CC*FF];
__device__ __align__(256) __half g_whpk  [(size_t)VPAD*CC];

// ======================= PTX helpers (sm_90 baseline only) =======================
__device__ __forceinline__ uint32_t smem_u32(const void* p) {
    uint32_t a;
    asm("{ .reg .u64 t; cvta.to.shared.u64 t, %1; cvt.u32.u64 %0, t; }"
        : "=r"(a) : "l"(p));
    return a;
}
#define MBAR_INIT(addr, cnt) \
    asm volatile("mbarrier.init.shared.b64 [%0], %1;" :: "r"(addr), "r"((uint32_t)(cnt)) : "memory")
#define MBAR_EXPECT_TX(addr, bytes) \
    asm volatile("mbarrier.arrive.expect_tx.shared.b64 _, [%0], %1;" \
                 :: "r"(addr), "r"((uint32_t)(bytes)) : "memory")

__device__ __forceinline__ void mbar_wait(uint32_t mbar, uint32_t parity) {
    uint32_t done;
    asm volatile(
        "{\n\t.reg .pred p;\n\t"
        "mbarrier.try_wait.parity.acquire.cta.shared::cta.b64 p, [%1], %2;\n\t"
        "selp.b32 %0, 1, 0, p;\n\t}"
        : "=r"(done) : "r"(mbar), "r"(parity) : "memory");
    if (!done) {
        asm volatile(
            "{\n\t.reg .pred P1;\n\t"
            "WAIT_LOOP_%=:\n\t"
            "mbarrier.try_wait.parity.acquire.cta.shared::cta.b64 P1, [%0], %1, 0x989680;\n\t"
            "@P1 bra.uni WAIT_DONE_%=;\n\t"
            "bra.uni WAIT_LOOP_%=;\n\t"
            "WAIT_DONE_%=:\n\t}"
            :: "r"(mbar), "r"(parity) : "memory");
    }
}
__device__ __forceinline__ void bulk_g2s(uint32_t dst, const void* src,
                                         uint32_t bytes, uint32_t mbar) {
    asm volatile(
        "cp.async.bulk.shared::cluster.global.mbarrier::complete_tx::bytes "
        "[%0], [%1], %2, [%3];"
        :: "r"(dst), "l"(src), "r"(bytes), "r"(mbar) : "memory");
}
__device__ __forceinline__ void ldsm4(uint32_t* r, uint32_t addr) {
    asm volatile("ldmatrix.sync.aligned.m8n8.x4.shared.b16 {%0,%1,%2,%3}, [%4];"
        : "=r"(r[0]), "=r"(r[1]), "=r"(r[2]), "=r"(r[3]) : "r"(addr));
}
__device__ __forceinline__ void mma16816h(float* d, const uint32_t* a, const uint32_t* b) {
    asm volatile(
        "mma.sync.aligned.m16n8k16.row.col.f32.f16.f16.f32 "
        "{%0,%1,%2,%3}, {%4,%5,%6,%7}, {%8,%9}, {%0,%1,%2,%3};"
        : "+f"(d[0]), "+f"(d[1]), "+f"(d[2]), "+f"(d[3])
        : "r"(a[0]), "r"(a[1]), "r"(a[2]), "r"(a[3]), "r"(b[0]), "r"(b[1]));
}

// 2-plane layout: element index for (blk128, kc, r): 128 halfs (hi 64 | lo 64)
__device__ __forceinline__ size_t pk_rowseg(int KC, int blk, int kc, int r) {
    return ((size_t)(blk * KC + kc) * 128 + r) * 128;
}
// 1-plane layout: 64 halfs per (r,kc)
__device__ __forceinline__ size_t pk1_rowseg(int KC, int blk, int kc, int r) {
    return ((size_t)(blk * KC + kc) * 128 + r) * 64;
}
__device__ __forceinline__ int pk_within(int r, int kk) {
    int ch = kk >> 3, w8 = kk & 7;
    return ((ch ^ (r & 7)) << 3) + w8;
}

// ======================= small kernels =======================
__global__ void embed_kernel(const int* __restrict__ tok,
                             const float* __restrict__ wte,
                             const float* __restrict__ wpe,
                             float* __restrict__ h) {
    int bt = blockIdx.x;
    int t  = bt % TT;
    int tk = tok[bt];
    const float* we = wte + (size_t)tk * CC;
    const float* wp = wpe + (size_t)t  * CC;
    float* hr = h + (size_t)bt * CC;
    for (int c = threadIdx.x; c < CC; c += blockDim.x)
        hr[c] = we[c] + wp[c];
}

// LayerNorm producing packed fp16 hi/lo A-operand (KC = 12)
__global__ void ln_pk_kernel(const float* __restrict__ x,
                             const float* __restrict__ gamma,
                             const float* __restrict__ beta,
                             __half* __restrict__ outpk) {
    int row = blockIdx.x;
    const float* xr = x + (size_t)row * CC;
    __shared__ float red[256];
    int tid = threadIdx.x;

    float s = 0.f;
    for (int c = tid; c < CC; c += 256) s += xr[c];
    red[tid] = s; __syncthreads();
    for (int o = 128; o > 0; o >>= 1) {
        if (tid < o) red[tid] += red[tid + o];
        __syncthreads();
    }
    float mu = red[0] * (1.0f / CC);
    __syncthreads();

    float v = 0.f;
    for (int c = tid; c < CC; c += 256) { float d = xr[c] - mu; v += d * d; }
    red[tid] = v; __syncthreads();
    for (int o = 128; o > 0; o >>= 1) {
        if (tid < o) red[tid] += red[tid + o];
        __syncthreads();
    }
    float rstd = rsqrtf(red[0] * (1.0f / CC) + 1e-5f);

    int blk = row >> 7, r = row & 127;
    for (int c = tid; c < CC; c += 256) {
        float val = (xr[c] - mu) * rstd * gamma[c] + beta[c];
        __half hi = __float2half_rn(val);
        __half lo = __float2half_rn(val - __half2float(hi));
        size_t base = pk_rowseg(12, blk, c >> 6, r);
        int w = pk_within(r, c & 63);
        outpk[base + w]      = hi;
        outpk[base + 64 + w] = lo;
    }
}

// LayerNorm producing packed fp16 SINGLE-plane A-operand (for LM head)
__global__ void ln_pk16_kernel(const float* __restrict__ x,
                               const float* __restrict__ gamma,
                               const float* __restrict__ beta,
                               __half* __restrict__ outpk) {
    int row = blockIdx.x;
    const float* xr = x + (size_t)row * CC;
    __shared__ float red[256];
    int tid = threadIdx.x;

    float s = 0.f;
    for (int c = tid; c < CC; c += 256) s += xr[c];
    red[tid] = s; __syncthreads();
    for (int o = 128; o > 0; o >>= 1) {
        if (tid < o) red[tid] += red[tid + o];
        __syncthreads();
    }
    float mu = red[0] * (1.0f / CC);
    __syncthreads();

    float v = 0.f;
    for (int c = tid; c < CC; c += 256) { float d = xr[c] - mu; v += d * d; }
    red[tid] = v; __syncthreads();
    for (int o = 128; o > 0; o >>= 1) {
        if (tid < o) red[tid] += red[tid + o];
        __syncthreads();
    }
    float rstd = rsqrtf(red[0] * (1.0f / CC) + 1e-5f);

    int blk = row >> 7, r = row & 127;
    for (int c = tid; c < CC; c += 256) {
        float val = (xr[c] - mu) * rstd * gamma[c] + beta[c];
        size_t base = pk1_rowseg(12, blk, c >> 6, r);
        int w = pk_within(r, c & 63);
        outpk[base + w] = __float2half_rn(val);
    }
}

// transpose + convert weight W[K,N](fp32) -> packed fp16 SINGLE-plane layout
__global__ __launch_bounds__(256)
void pack_w16_kernel(const float* __restrict__ W, __half* __restrict__ Bpk,
                     int K, int N, int n0out) {
    __shared__ float sm[64][65];
    int tid = threadIdx.x;
    int n0 = blockIdx.x * 64;
    int k0 = blockIdx.y * 64;
    int KC = K >> 6;

    for (int idx = tid; idx < 64 * 64; idx += 256) {
        int kr = idx >> 6, nc = idx & 63;
        int gn = n0 + nc;
        sm[kr][nc] = (gn < N) ? W[(size_t)(k0 + kr) * N + gn] : 0.f;
    }
    __syncthreads();

    for (int g = tid; g < 512; g += 256) {
        int n = g >> 3, ch = g & 7;
        int gn = n0out + n0 + n;
        int bn = gn >> 7, r = gn & 127;
        size_t base = pk1_rowseg(KC, bn, blockIdx.y, r);
        int w = (ch ^ (r & 7)) << 3;
        union { uint4 v; __half b[8]; } uh;
#pragma unroll
        for (int j = 0; j < 8; ++j)
            uh.b[j] = __float2half_rn(sm[ch * 8 + j][n]);
        *(uint4*)(Bpk + base + w) = uh.v;
    }
}

// ======================= HMMA GEMM (fp16, 2-term: AhB + AlB) =======================
// A: packed fp16 hi/lo 2-plane (256B rows). B: packed fp16 single plane (128B rows).
#define EPI_NONE 0
#define EPI_GELU_PK 2
#define EPI_RES 3

#define STAGES 3
#define HG_SMEM_128 (STAGES * (32768 + 16384))
#define HG_SMEM_64  (STAGES * (16384 + 16384))

template<int EPI, int IMS>
__global__ __launch_bounds__(256, 1)
void hgemm(const __half* __restrict__ Apk,
           const __half* __restrict__ Bpk,
           const float* __restrict__ bias,
           const float* __restrict__ Res,
           float* __restrict__ outf,
           __half* __restrict__ outpk,
           int N, int K, int Nl) {
    constexpr int ABYTES = IMS * 8192;     // BM rows x 256B
    constexpr int BBYTES = 16384;          // 128 rows x 128B
    constexpr int SSTRIDE = ABYTES + BBYTES;
    extern __shared__ __align__(1024) char smem[];
    __shared__ __align__(8) uint64_t s_full[STAGES];

    int tid = threadIdx.x;
    int lane = tid & 31, w = tid >> 5;
    int wm = w & 1, wn = w >> 1;      // warp grid 2(M) x 4(N)
    int bm = blockIdx.y, bn = blockIdx.x;
    int KC = K >> 6;
    uint32_t sbase = smem_u32(smem);
    uint32_t mb0 = smem_u32(&s_full[0]);

    int blkA = (IMS == 4) ? bm : (bm >> 1);
    int roff = (IMS == 4) ? 0 : ((bm & 1) << 6);

    if (tid == 0) {
#pragma unroll
        for (int s = 0; s < STAGES; ++s) MBAR_INIT(mb0 + s * 8, 1);
    }
    __syncthreads();

    float acc[IMS][4][4];
#pragma unroll
    for (int i = 0; i < IMS; ++i)
#pragma unroll
        for (int j = 0; j < 4; ++j)
#pragma unroll
            for (int q = 0; q < 4; ++q) acc[i][j][q] = 0.f;

    const int la15 = lane & 15, lahi = lane >> 4;
    const int bmx = lane >> 3;
    const int brow_base = wn * 32 + ((bmx >> 1) << 3) + (lane & 7);
    const int bcs = bmx & 1;

    if (tid == 0) {
#pragma unroll
        for (int c = 0; c < STAGES - 1; ++c) {
            uint32_t m = mb0 + c * 8;
            MBAR_EXPECT_TX(m, SSTRIDE);
            bulk_g2s(sbase + c * SSTRIDE,
                     Apk + (((size_t)(blkA * KC + c)) * 128 + roff) * 128, ABYTES, m);
            bulk_g2s(sbase + c * SSTRIDE + ABYTES,
                     Bpk + ((size_t)bn * KC + c) * 8192, BBYTES, m);
        }
    }

    for (int c = 0; c < KC; ++c) {
        int s = c % STAGES;
        mbar_wait(mb0 + s * 8, (c / STAGES) & 1);

        if (tid == 0) {
            int cn = c + STAGES - 1;
            if (cn < KC) {
                int sn = cn % STAGES;
                uint32_t m = mb0 + sn * 8;
                MBAR_EXPECT_TX(m, SSTRIDE);
                bulk_g2s(sbase + sn * SSTRIDE,
                         Apk + (((size_t)(blkA * KC + cn)) * 128 + roff) * 128, ABYTES, m);
                bulk_g2s(sbase + sn * SSTRIDE + ABYTES,
                         Bpk + ((size_t)bn * KC + cn) * 8192, BBYTES, m);
            }
        }

        uint32_t Ab = sbase + s * SSTRIDE;
        uint32_t Bb = Ab + ABYTES;

#pragma unroll
        for (int kh = 0; kh < 4; ++kh) {
            uint32_t af[2][IMS][4];   // [plane][im][4]
            uint32_t bf_[4][2];
#pragma unroll
            for (int im = 0; im < IMS; ++im) {
                int r = wm * (IMS * 16) + im * 16 + la15;
                int cch = kh * 2 + lahi;
                uint32_t off = (uint32_t)(r * 256 + (((cch ^ (r & 7))) << 4));
                ldsm4(af[0][im], Ab + off);
                ldsm4(af[1][im], Ab + off + 128);
            }
#pragma unroll
            for (int g2 = 0; g2 < 2; ++g2) {
                int nr = brow_base + g2 * 16;
                int cch = kh * 2 + bcs;
                uint32_t off = (uint32_t)(nr * 128 + (((cch ^ (nr & 7))) << 4));
                uint32_t t4[4];
                ldsm4(t4, Bb + off);
                bf_[g2 * 2][0]     = t4[0];
                bf_[g2 * 2][1]     = t4[1];
                bf_[g2 * 2 + 1][0] = t4[2];
                bf_[g2 * 2 + 1][1] = t4[3];
            }
#pragma unroll
            for (int im = 0; im < IMS; ++im)
#pragma unroll
                for (int in_ = 0; in_ < 4; ++in_) {
                    mma16816h(acc[im][in_], af[0][im], bf_[in_]);
                    mma16816h(acc[im][in_], af[1][im], bf_[in_]);
                }
        }
        __syncthreads();
    }

    // ---------------- epilogue ----------------
    int r0 = bm * (IMS * 32) + wm * (IMS * 16) + (lane >> 2);
    int c0base = bn * 128 + wn * 32 + 2 * (lane & 3);
    int KCo = N >> 6;

#pragma unroll
    for (int im = 0; im < IMS; ++im) {
#pragma unroll
        for (int half = 0; half < 2; ++half) {
            int row = r0 + im * 16 + half * 8;
#pragma unroll
            for (int in_ = 0; in_ < 4; ++in_) {
                int col = c0base + in_ * 8;
                float v0 = acc[im][in_][half * 2 + 0];
                float v1 = acc[im][in_][half * 2 + 1];
                if (EPI == EPI_NONE) {
                    *(float2*)(outf + (size_t)row * Nl + col) = make_float2(v0, v1);
                } else if (EPI == EPI_RES) {
                    const float* rr = Res + (size_t)row * Nl + col;
                    v0 += bias[col]     + rr[0];
                    v1 += bias[col + 1] + rr[1];
                    *(float2*)(outf + (size_t)row * Nl + col) = make_float2(v0, v1);
                } else if (EPI == EPI_GELU_PK) {
                    v0 += bias[col];
                    v1 += bias[col + 1];
                    v0 = 0.5f * v0 * (1.0f + erff(v0 * 0.7071067811865476f));
                    v1 = 0.5f * v1 * (1.0f + erff(v1 * 0.7071067811865476f));
                    __half h0 = __float2half_rn(v0);
                    __half h1 = __float2half_rn(v1);
                    __half l0 = __float2half_rn(v0 - __half2float(h0));
                    __half l1 = __float2half_rn(v1 - __half2float(h1));
                    int blk = row >> 7, r = row & 127;
                    size_t base = pk_rowseg(KCo, blk, col >> 6, r);
                    int wi = pk_within(r, col & 63);
                    *(__half2*)(outpk + base + wi)      = __half2(h0, h1);
                    *(__half2*)(outpk + base + 64 + wi) = __half2(l0, l1);
                }
            }
        }
    }
}

// ======================= LM head GEMM (single-pass fp16) =======================
#define HEAD_SMEM (STAGES * (16384 + 16384))

__global__ __launch_bounds__(256, 1)
void hgemm_head(const __half* __restrict__ Apk,
                const __half* __restrict__ Bpk,
                const float* __restrict__ bias,
                float* __restrict__ outf,
                int N, int K, int Nl) {
    constexpr int ABYTES = 16384;
    constexpr int BBYTES = 16384;
    constexpr int SSTRIDE = ABYTES + BBYTES;
    extern __shared__ __align__(1024) char smem[];
    __shared__ __align__(8) uint64_t s_full[STAGES];

    int tid = threadIdx.x;
    int lane = tid & 31, w = tid >> 5;
    int wm = w & 1, wn = w >> 1;
    int bm = blockIdx.y, bn = blockIdx.x;
    int KC = K >> 6;
    uint32_t sbase = smem_u32(smem);
    uint32_t mb0 = smem_u32(&s_full[0]);

    if (tid == 0) {
#pragma unroll
        for (int s = 0; s < STAGES; ++s) MBAR_INIT(mb0 + s * 8, 1);
    }
    __syncthreads();

    float acc[4][4][4];
#pragma unroll
    for (int i = 0; i < 4; ++i)
#pragma unroll
        for (int j = 0; j < 4; ++j)
#pragma unroll
            for (int q = 0; q < 4; ++q) acc[i][j][q] = 0.f;

    const int la15 = lane & 15, lahi = lane >> 4;
    const int bmx = lane >> 3;
    const int brow_base = wn * 32 + ((bmx >> 1) << 3) + (lane & 7);
    const int bcs = bmx & 1;

    if (tid == 0) {
#pragma unroll
        for (int c = 0; c < STAGES - 1; ++c) {
            uint32_t m = mb0 + c * 8;
            MBAR_EXPECT_TX(m, SSTRIDE);
            bulk_g2s(sbase + c * SSTRIDE,
                     Apk + ((size_t)bm * KC + c) * 8192, ABYTES, m);
            bulk_g2s(sbase + c * SSTRIDE + ABYTES,
                     Bpk + ((size_t)bn * KC + c) * 8192, BBYTES, m);
        }
    }

    for (int c = 0; c < KC; ++c) {
        int s = c % STAGES;
        mbar_wait(mb0 + s * 8, (c / STAGES) & 1);

        if (tid == 0) {
            int cn = c + STAGES - 1;
            if (cn < KC) {
                int sn = cn % STAGES;
                uint32_t m = mb0 + sn * 8;
                MBAR_EXPECT_TX(m, SSTRIDE);
                bulk_g2s(sbase + sn * SSTRIDE,
                         Apk + ((size_t)bm * KC + cn) * 8192, ABYTES, m);
                bulk_g2s(sbase + sn * SSTRIDE + ABYTES,
                         Bpk + ((size_t)bn * KC + cn) * 8192, BBYTES, m);
            }
        }

        uint32_t Ab = sbase + s * SSTRIDE;
        uint32_t Bb = Ab + ABYTES;

#pragma unroll
        for (int kh = 0; kh < 4; ++kh) {
            uint32_t af[4][4];
            uint32_t bf_[4][2];
#pragma unroll
            for (int im = 0; im < 4; ++im) {
                int r = wm * 64 + im * 16 + la15;
                int cch = kh * 2 + lahi;
                uint32_t off = (uint32_t)(r * 128 + (((cch ^ (r & 7))) << 4));
                ldsm4(af[im], Ab + off);
            }
#pragma unroll
            for (int g2 = 0; g2 < 2; ++g2) {
                int nr = brow_base + g2 * 16;
                int cch = kh * 2 + bcs;
                uint32_t off = (uint32_t)(nr * 128 + (((cch ^ (nr & 7))) << 4));
                uint32_t t4[4];
                ldsm4(t4, Bb + off);
                bf_[g2 * 2][0]     = t4[0];
                bf_[g2 * 2][1]     = t4[1];
                bf_[g2 * 2 + 1][0] = t4[2];
                bf_[g2 * 2 + 1][1] = t4[3];
            }
#pragma unroll
            for (int im = 0; im < 4; ++im)
#pragma unroll
                for (int in_ = 0; in_ < 4; ++in_)
                    mma16816h(acc[im][in_], af[im], bf_[in_]);
        }
        __syncthreads();
    }

    int r0 = bm * 128 + wm * 64 + (lane >> 2);
    int c0base = bn * 128 + wn * 32 + 2 * (lane & 3);
#pragma unroll
    for (int im = 0; im < 4; ++im) {
#pragma unroll
        for (int half = 0; half < 2; ++half) {
            int row = r0 + im * 16 + half * 8;
#pragma unroll
            for (int in_ = 0; in_ < 4; ++in_) {
                int col = c0base + in_ * 8;
                float v0 = acc[im][in_][half * 2 + 0];
                float v1 = acc[im][in_][half * 2 + 1];
                if (col < Nl)     outf[(size_t)row * Nl + col]     = v0 + bias[col];
                if (col + 1 < Nl) outf[(size_t)row * Nl + col + 1] = v1 + bias[col + 1];
            }
        }
    }
}

// ---------------- tiled causal attention: 64 q-rows per block ----------------
#define ATT_PAD 68
#define ATT_ROW (64 * ATT_PAD)
#define ATT_SMEM (4 * ATT_ROW * 4)

__global__ __launch_bounds__(256)
void attn_kernel(const float* __restrict__ QKV,
                 __half* __restrict__ Opk) {
    extern __shared__ float asm_[];
    float* sq = asm_;
    float* sk = asm_ + ATT_ROW;
    float* sv = asm_ + 2 * ATT_ROW;
    float* sp = asm_ + 3 * ATT_ROW;

    int tid = threadIdx.x;
    int q0 = blockIdx.x * 64;
    int hh = blockIdx.y;
    int b  = blockIdx.z;
    int qr = tid >> 2, dg = tid & 3;
    int qg = q0 + qr;

    const float scale = rsqrtf((float)CC);

    {
        int r = tid >> 4, c4 = (tid & 15) * 4;
#pragma unroll
        for (int it = 0; it < 4; ++it, r += 16) {
            *(float4*)&sq[r * ATT_PAD + c4] =
                *(const float4*)(QKV + ((size_t)(b * TT + q0 + r)) * NQKV + hh * DD + c4);
        }
    }

    float m = -INFINITY, l = 0.f;
    float acc[16];
#pragma unroll
    for (int i = 0; i < 16; ++i) acc[i] = 0.f;

    for (int j0 = 0; j0 <= q0; j0 += 64) {
        __syncthreads();
        {
            int r = tid >> 4, c4 = (tid & 15) * 4;
#pragma unroll
            for (int it = 0; it < 4; ++it, r += 16) {
                size_t rb = ((size_t)(b * TT + j0 + r)) * NQKV + hh * DD + c4;
                *(float4*)&sk[r * ATT_PAD + c4] = *(const float4*)(QKV + rb + CC);
                *(float4*)&sv[r * ATT_PAD + c4] = *(const float4*)(QKV + rb + 2 * CC);
            }
        }
        __syncthreads();

        float s[16];
#pragma unroll
        for (int jj = 0; jj < 16; ++jj) s[jj] = 0.f;
        const float* qrow = sq + qr * ATT_PAD;
#pragma unroll
        for (int k4 = 0; k4 < 16; ++k4) {
            float4 qv = *(const float4*)(qrow + k4 * 4);
#pragma unroll
            for (int jj = 0; jj < 16; ++jj) {
                int j = jj * 4 + dg;
                float4 kv = *(const float4*)(sk + j * ATT_PAD + k4 * 4);
                s[jj] = fmaf(qv.x, kv.x, s[jj]);
                s[jj] = fmaf(qv.y, kv.y, s[jj]);
                s[jj] = fmaf(qv.z, kv.z, s[jj]);
                s[jj] = fmaf(qv.w, kv.w, s[jj]);
            }
        }

        float tmax = -INFINITY;
#pragma unroll
        for (int jj = 0; jj < 16; ++jj) {
            int j = jj * 4 + dg;
            s[jj] = (j0 + j <= qg) ? s[jj] * scale : -INFINITY;
            tmax = fmaxf(tmax, s[jj]);
        }
        tmax = fmaxf(tmax, __shfl_xor_sync(0xFFFFFFFF, tmax, 1));
        tmax = fmaxf(tmax, __shfl_xor_sync(0xFFFFFFFF, tmax, 2));

        float newm = fmaxf(m, tmax);
        float corr = __expf(m - newm);
        float lp = 0.f;
#pragma unroll
        for (int jj = 0; jj < 16; ++jj) {
            int j = jj * 4 + dg;
            float p = __expf(s[jj] - newm);
            sp[qr * ATT_PAD + j] = p;
            lp += p;
        }
        lp += __shfl_xor_sync(0xFFFFFFFF, lp, 1);
        lp += __shfl_xor_sync(0xFFFFFFFF, lp, 2);
        l = l * corr + lp;
        m = newm;
#pragma unroll
        for (int i = 0; i < 16; ++i) acc[i] *= corr;

        __syncthreads();

        const float* prow = sp + qr * ATT_PAD;
#pragma unroll 8
        for (int j = 0; j < 64; ++j) {
            float pj = prow[j];
            const float* vrow = sv + j * ATT_PAD + dg * 16;
            float4 v0 = *(const float4*)(vrow);
            float4 v1 = *(const float4*)(vrow + 4);
            float4 v2 = *(const float4*)(vrow + 8);
            float4 v3 = *(const float4*)(vrow + 12);
            acc[0]  = fmaf(pj, v0.x, acc[0]);  acc[1]  = fmaf(pj, v0.y, acc[1]);
            acc[2]  = fmaf(pj, v0.z, acc[2]);  acc[3]  = fmaf(pj, v0.w, acc[3]);
            acc[4]  = fmaf(pj, v1.x, acc[4]);  acc[5]  = fmaf(pj, v1.y, acc[5]);
            acc[6]  = fmaf(pj, v1.z, acc[6]);  acc[7]  = fmaf(pj, v1.w, acc[7]);
            acc[8]  = fmaf(pj, v2.x, acc[8]);  acc[9]  = fmaf(pj, v2.y, acc[9]);
            acc[10] = fmaf(pj, v2.z, acc[10]); acc[11] = fmaf(pj, v2.w, acc[11]);
            acc[12] = fmaf(pj, v3.x, acc[12]); acc[13] = fmaf(pj, v3.y, acc[13]);
            acc[14] = fmaf(pj, v3.z, acc[14]); acc[15] = fmaf(pj, v3.w, acc[15]);
        }
    }

    float inv = 1.0f / l;
    int rowg = b * TT + qg;
    int blk = rowg >> 7, r = rowg & 127;
    size_t base = pk_rowseg(12, blk, hh, r);
#pragma unroll
    for (int dd = 0; dd < 16; dd += 2) {
        int d = dg * 16 + dd;
        float v0 = acc[dd] * inv;
        float v1 = acc[dd + 1] * inv;
        __half h0 = __float2half_rn(v0);
        __half h1 = __float2half_rn(v1);
        __half l0 = __float2half_rn(v0 - __half2float(h0));
        __half l1 = __float2half_rn(v1 - __half2float(h1));
        int wi = pk_within(r, d);
        *(__half2*)(Opk + base + wi)      = __half2(h0, h1);
        *(__half2*)(Opk + base + 64 + wi) = __half2(l0, l1);
    }
}

// ======================= launch =======================
extern "C" void kernel_launch(void* const* d_in, const int* in_sizes, int n_in,
                              void* d_out, int out_size) {
    const int*   tokens = (const int*)  d_in[0];
    const float* wte    = (const float*)d_in[1];
    const float* wpe    = (const float*)d_in[2];
    const float* Wq     = (const float*)d_in[3];
    const float* Wk     = (const float*)d_in[4];
    const float* Wv     = (const float*)d_in[5];
    const float* Wo     = (const float*)d_in[6];
    const float* bo     = (const float*)d_in[7];
    const float* ln1g   = (const float*)d_in[8];
    const float* ln1b   = (const float*)d_in[9];
    const float* ln2g   = (const float*)d_in[10];
    const float* ln2b   = (const float*)d_in[11];
    const float* W1     = (const float*)d_in[12];
    const float* b1     = (const float*)d_in[13];
    const float* W2     = (const float*)d_in[14];
    const float* b2     = (const float*)d_in[15];
    const float* lnfg   = (const float*)d_in[16];
    const float* lnfb   = (const float*)d_in[17];
    const float* Wh     = (const float*)d_in[18];
    const float* bh     = (const float*)d_in[19];
    float* out = (float*)d_out;

    static bool attrs_set = false;
    if (!attrs_set) {
        cudaFuncSetAttribute(hgemm<EPI_NONE, 4>,    cudaFuncAttributeMaxDynamicSharedMemorySize, HG_SMEM_128);
        cudaFuncSetAttribute(hgemm<EPI_GELU_PK, 4>, cudaFuncAttributeMaxDynamicSharedMemorySize, HG_SMEM_128);
        cudaFuncSetAttribute(hgemm<EPI_RES, 2>,     cudaFuncAttributeMaxDynamicSharedMemorySize, HG_SMEM_64);
        cudaFuncSetAttribute(hgemm_head,            cudaFuncAttributeMaxDynamicSharedMemorySize, HEAD_SMEM);
        cudaFuncSetAttribute(attn_kernel,           cudaFuncAttributeMaxDynamicSharedMemorySize, ATT_SMEM);
        attrs_set = true;
    }

    float *h, *qkv;
    __half *xpk, *opk, *mpk, *wqkvpk, *wopk, *w1pk, *w2pk, *whpk;
    cudaGetSymbolAddress((void**)&h,      g_h);
    cudaGetSymbolAddress((void**)&qkv,    g_qkv);
    cudaGetSymbolAddress((void**)&xpk,    g_xpk);
    cudaGetSymbolAddress((void**)&opk,    g_opk);
    cudaGetSymbolAddress((void**)&mpk,    g_mpk);
    cudaGetSymbolAddress((void**)&wqkvpk, g_wqkvpk);
    cudaGetSymbolAddress((void**)&wopk,   g_wopk);
    cudaGetSymbolAddress((void**)&w1pk,   g_w1pk);
    cudaGetSymbolAddress((void**)&w2pk,   g_w2pk);
    cudaGetSymbolAddress((void**)&whpk,   g_whpk);

    dim3 gQKV(NQKV / 128, MM / 128);   // (18, 32)
    dim3 gC64(CC / 128, MM / 64);      // (6, 64)  BM=64
    dim3 gF(FF / 128, MM / 128);       // (24, 32)
    dim3 gV(VPAD / 128, MM / 128);     // (393, 32)

    dim3 pCC(12, 12);
    dim3 pW1(48, 12);
    dim3 pW2(12, 48);
    dim3 pWh(786, 12);

    embed_kernel<<<MM, 256>>>(tokens, wte, wpe, h);
    pack_w16_kernel<<<pWh, 256>>>(Wh, whpk, CC, VV, 0);

    for (int l = 0; l < LL; l++) {
        pack_w16_kernel<<<pCC, 256>>>(Wq + (size_t)l * CC * CC, wqkvpk, CC, CC, 0);
        pack_w16_kernel<<<pCC, 256>>>(Wk + (size_t)l * CC * CC, wqkvpk, CC, CC, 768);
        pack_w16_kernel<<<pCC, 256>>>(Wv + (size_t)l * CC * CC, wqkvpk, CC, CC, 1536);
        pack_w16_kernel<<<pCC, 256>>>(Wo + (size_t)l * CC * CC, wopk, CC, CC, 0);
        pack_w16_kernel<<<pW1, 256>>>(W1 + (size_t)l * CC * FF, w1pk, CC, FF, 0);
        pack_w16_kernel<<<pW2, 256>>>(W2 + (size_t)l * FF * CC, w2pk, FF, CC, 0);

        ln_pk_kernel<<<MM, 256>>>(h, ln1g + l * CC, ln1b + l * CC, xpk);
        hgemm<EPI_NONE, 4><<<gQKV, 256, HG_SMEM_128>>>(xpk, wqkvpk, nullptr, nullptr,
                                                       qkv, nullptr, NQKV, CC, NQKV);

        attn_kernel<<<dim3(TT / 64, HH, BB), 256, ATT_SMEM>>>(qkv, opk);

        hgemm<EPI_RES, 2><<<gC64, 256, HG_SMEM_64>>>(opk, wopk, bo + l * CC, h,
                                                     h, nullptr, CC, CC, CC);

        ln_pk_kernel<<<MM, 256>>>(h, ln2g + l * CC, ln2b + l * CC, xpk);
        hgemm<EPI_GELU_PK, 4><<<gF, 256, HG_SMEM_128>>>(xpk, w1pk, b1 + l * FF, nullptr,
                                                        nullptr, mpk, FF, CC, FF);
        hgemm<EPI_RES, 2><<<gC64, 256, HG_SMEM_64>>>(mpk, w2pk, b2 + l * CC, h,
                                                     h, nullptr, CC, FF, CC);
    }

    ln_pk16_kernel<<<MM, 256>>>(h, lnfg, lnfb, xpk);
    hgemm_head<<<gV, 256, HEAD_SMEM>>>(xpk, whpk, bh, out, VPAD, CC, VV);
}

// round 14
// speedup vs baseline: 1.3646x; 1.0486x over previous
#include <cuda_runtime.h>
#include <cuda_bf16.h>
#include <cuda_fp16.h>
#include <math.h>
#include <stdint.h>

// Problem dims
#define BB 4
#define TT 1024
#define CC 768
#define HH 12
#define LL 6
#define VV 50257
#define DD 64
#define FF 3072
#define MM (BB*TT)        // 4096 rows
#define NQKV 2304
#define VPAD 50304        // 393*128

// ---------------- scratch (device globals; allocation-free) ----------------
__device__ float g_h[(size_t)MM*CC];
__device__ float g_qkv[(size_t)MM*NQKV];
// packed fp16 operand buffers
// 2-plane (hi/lo) activations: [blk128][K/64][r:128][pl:2][64] halfs
__device__ __align__(256) __half g_xpk [(size_t)MM*CC*2];   // also 1-plane for head
__device__ __align__(256) __half g_opk [(size_t)MM*CC*2];
__device__ __align__(256) __half g_mpk [(size_t)MM*FF*2];
// 1-plane weights, per-layer: [layer][blkN128][K/64][r:128][64] halfs
__device__ __align__(256) __half g_wqkvpk[(size_t)LL*NQKV*CC];
__device__ __align__(256) __half g_wopk  [(size_t)LL*CC*CC];
__device__ __align__(256) __half g_w1pk  [(size_t)LL*FF*CC];
__device__ __align__(256) __half g_w2pk  [(size_t)LL*CC*FF];
__device__ __align__(256) __half g_whpk  [(size_t)VPAD*CC];

// ======================= PTX helpers (sm_90 baseline only) =======================
__device__ __forceinline__ uint32_t smem_u32(const void* p) {
    uint32_t a;
    asm("{ .reg .u64 t; cvta.to.shared.u64 t, %1; cvt.u32.u64 %0, t; }"
        : "=r"(a) : "l"(p));
    return a;
}
#define MBAR_INIT(addr, cnt) \
    asm volatile("mbarrier.init.shared.b64 [%0], %1;" :: "r"(addr), "r"((uint32_t)(cnt)) : "memory")
#define MBAR_EXPECT_TX(addr, bytes) \
    asm volatile("mbarrier.arrive.expect_tx.shared.b64 _, [%0], %1;" \
                 :: "r"(addr), "r"((uint32_t)(bytes)) : "memory")

__device__ __forceinline__ void mbar_wait(uint32_t mbar, uint32_t parity) {
    uint32_t done;
    asm volatile(
        "{\n\t.reg .pred p;\n\t"
        "mbarrier.try_wait.parity.acquire.cta.shared::cta.b64 p, [%1], %2;\n\t"
        "selp.b32 %0, 1, 0, p;\n\t}"
        : "=r"(done) : "r"(mbar), "r"(parity) : "memory");
    if (!done) {
        asm volatile(
            "{\n\t.reg .pred P1;\n\t"
            "WAIT_LOOP_%=:\n\t"
            "mbarrier.try_wait.parity.acquire.cta.shared::cta.b64 P1, [%0], %1, 0x989680;\n\t"
            "@P1 bra.uni WAIT_DONE_%=;\n\t"
            "bra.uni WAIT_LOOP_%=;\n\t"
            "WAIT_DONE_%=:\n\t}"
            :: "r"(mbar), "r"(parity) : "memory");
    }
}
__device__ __forceinline__ void bulk_g2s(uint32_t dst, const void* src,
                                         uint32_t bytes, uint32_t mbar) {
    asm volatile(
        "cp.async.bulk.shared::cluster.global.mbarrier::complete_tx::bytes "
        "[%0], [%1], %2, [%3];"
        :: "r"(dst), "l"(src), "r"(bytes), "r"(mbar) : "memory");
}
__device__ __forceinline__ void ldsm4(uint32_t* r, uint32_t addr) {
    asm volatile("ldmatrix.sync.aligned.m8n8.x4.shared.b16 {%0,%1,%2,%3}, [%4];"
        : "=r"(r[0]), "=r"(r[1]), "=r"(r[2]), "=r"(r[3]) : "r"(addr));
}
__device__ __forceinline__ void mma16816h(float* d, const uint32_t* a, const uint32_t* b) {
    asm volatile(
        "mma.sync.aligned.m16n8k16.row.col.f32.f16.f16.f32 "
        "{%0,%1,%2,%3}, {%4,%5,%6,%7}, {%8,%9}, {%0,%1,%2,%3};"
        : "+f"(d[0]), "+f"(d[1]), "+f"(d[2]), "+f"(d[3])
        : "r"(a[0]), "r"(a[1]), "r"(a[2]), "r"(a[3]), "r"(b[0]), "r"(b[1]));
}

// 2-plane layout: element index for (blk128, kc, r): 128 halfs (hi 64 | lo 64)
__device__ __forceinline__ size_t pk_rowseg(int KC, int blk, int kc, int r) {
    return ((size_t)(blk * KC + kc) * 128 + r) * 128;
}
// 1-plane layout: 64 halfs per (r,kc)
__device__ __forceinline__ size_t pk1_rowseg(int KC, int blk, int kc, int r) {
    return ((size_t)(blk * KC + kc) * 128 + r) * 64;
}
__device__ __forceinline__ int pk_within(int r, int kk) {
    int ch = kk >> 3, w8 = kk & 7;
    return ((ch ^ (r & 7)) << 3) + w8;
}

// ======================= small kernels =======================
__global__ void embed_kernel(const int* __restrict__ tok,
                             const float* __restrict__ wte,
                             const float* __restrict__ wpe,
                             float* __restrict__ h) {
    int bt = blockIdx.x;
    int t  = bt % TT;
    int tk = tok[bt];
    const float* we = wte + (size_t)tk * CC;
    const float* wp = wpe + (size_t)t  * CC;
    float* hr = h + (size_t)bt * CC;
    for (int c = threadIdx.x; c < CC; c += blockDim.x)
        hr[c] = we[c] + wp[c];
}

// LayerNorm (warp per row) producing packed fp16 hi/lo A-operand (KC = 12)
__global__ __launch_bounds__(256)
void ln_pk_kernel(const float* __restrict__ x,
                  const float* __restrict__ gamma,
                  const float* __restrict__ beta,
                  __half* __restrict__ outpk) {
    int wid = threadIdx.x >> 5, lane = threadIdx.x & 31;
    int row = blockIdx.x * 8 + wid;
    const float* xr = x + (size_t)row * CC;

    float4 v[6];
    float s = 0.f;
#pragma unroll
    for (int k = 0; k < 6; ++k) {
        v[k] = *(const float4*)(xr + k * 128 + lane * 4);
        s += v[k].x + v[k].y + v[k].z + v[k].w;
    }
#pragma unroll
    for (int o = 16; o; o >>= 1) s += __shfl_xor_sync(0xFFFFFFFFu, s, o);
    float mu = s * (1.0f / CC);

    float var = 0.f;
#pragma unroll
    for (int k = 0; k < 6; ++k) {
        float dx = v[k].x - mu, dy = v[k].y - mu, dz = v[k].z - mu, dw = v[k].w - mu;
        var += dx * dx + dy * dy + dz * dz + dw * dw;
    }
#pragma unroll
    for (int o = 16; o; o >>= 1) var += __shfl_xor_sync(0xFFFFFFFFu, var, o);
    float rstd = rsqrtf(var * (1.0f / CC) + 1e-5f);

    int blk = row >> 7, r = row & 127;
#pragma unroll
    for (int k = 0; k < 6; ++k) {
        int cb = k * 128 + lane * 4;
        float4 g4 = *(const float4*)(gamma + cb);
        float4 b4 = *(const float4*)(beta + cb);
        float y0 = (v[k].x - mu) * rstd * g4.x + b4.x;
        float y1 = (v[k].y - mu) * rstd * g4.y + b4.y;
        float y2 = (v[k].z - mu) * rstd * g4.z + b4.z;
        float y3 = (v[k].w - mu) * rstd * g4.w + b4.w;
        __half h0 = __float2half_rn(y0), h1 = __float2half_rn(y1);
        __half h2 = __float2half_rn(y2), h3 = __float2half_rn(y3);
        __half l0 = __float2half_rn(y0 - __half2float(h0));
        __half l1 = __float2half_rn(y1 - __half2float(h1));
        __half l2 = __float2half_rn(y2 - __half2float(h2));
        __half l3 = __float2half_rn(y3 - __half2float(h3));
        size_t base = pk_rowseg(12, blk, cb >> 6, r);
        int kk = cb & 63;
        int w0 = pk_within(r, kk);
        int w2 = pk_within(r, kk + 2);
        *(__half2*)(outpk + base + w0)        = __half2(h0, h1);
        *(__half2*)(outpk + base + w2)        = __half2(h2, h3);
        *(__half2*)(outpk + base + 64 + w0)   = __half2(l0, l1);
        *(__half2*)(outpk + base + 64 + w2)   = __half2(l2, l3);
    }
}

// LayerNorm (warp per row) producing packed fp16 SINGLE-plane A-operand (LM head)
__global__ __launch_bounds__(256)
void ln_pk16_kernel(const float* __restrict__ x,
                    const float* __restrict__ gamma,
                    const float* __restrict__ beta,
                    __half* __restrict__ outpk) {
    int wid = threadIdx.x >> 5, lane = threadIdx.x & 31;
    int row = blockIdx.x * 8 + wid;
    const float* xr = x + (size_t)row * CC;

    float4 v[6];
    float s = 0.f;
#pragma unroll
    for (int k = 0; k < 6; ++k) {
        v[k] = *(const float4*)(xr + k * 128 + lane * 4);
        s += v[k].x + v[k].y + v[k].z + v[k].w;
    }
#pragma unroll
    for (int o = 16; o; o >>= 1) s += __shfl_xor_sync(0xFFFFFFFFu, s, o);
    float mu = s * (1.0f / CC);

    float var = 0.f;
#pragma unroll
    for (int k = 0; k < 6; ++k) {
        float dx = v[k].x - mu, dy = v[k].y - mu, dz = v[k].z - mu, dw = v[k].w - mu;
        var += dx * dx + dy * dy + dz * dz + dw * dw;
    }
#pragma unroll
    for (int o = 16; o; o >>= 1) var += __shfl_xor_sync(0xFFFFFFFFu, var, o);
    float rstd = rsqrtf(var * (1.0f / CC) + 1e-5f);

    int blk = row >> 7, r = row & 127;
#pragma unroll
    for (int k = 0; k < 6; ++k) {
        int cb = k * 128 + lane * 4;
        float4 g4 = *(const float4*)(gamma + cb);
        float4 b4 = *(const float4*)(beta + cb);
        __half h0 = __float2half_rn((v[k].x - mu) * rstd * g4.x + b4.x);
        __half h1 = __float2half_rn((v[k].y - mu) * rstd * g4.y + b4.y);
        __half h2 = __float2half_rn((v[k].z - mu) * rstd * g4.z + b4.z);
        __half h3 = __float2half_rn((v[k].w - mu) * rstd * g4.w + b4.w);
        size_t base = pk1_rowseg(12, blk, cb >> 6, r);
        int kk = cb & 63;
        int w0 = pk_within(r, kk);
        int w2 = pk_within(r, kk + 2);
        *(__half2*)(outpk + base + w0) = __half2(h0, h1);
        *(__half2*)(outpk + base + w2) = __half2(h2, h3);
    }
}

// transpose + convert weight W[K,N](fp32) -> packed fp16 SINGLE-plane layout.
// Batched over layers via blockIdx.z (W += z*wstr, Bpk += z*pstr).
__global__ __launch_bounds__(256)
void pack_w16_kernel(const float* __restrict__ W, __half* __restrict__ Bpk,
                     int K, int N, int n0out, size_t wstr, size_t pstr) {
    __shared__ float sm[64][65];
    int tid = threadIdx.x;
    int n0 = blockIdx.x * 64;
    int k0 = blockIdx.y * 64;
    int KC = K >> 6;
    const float* Wl = W + (size_t)blockIdx.z * wstr;
    __half* Bl = Bpk + (size_t)blockIdx.z * pstr;

    for (int idx = tid; idx < 64 * 64; idx += 256) {
        int kr = idx >> 6, nc = idx & 63;
        int gn = n0 + nc;
        sm[kr][nc] = (gn < N) ? Wl[(size_t)(k0 + kr) * N + gn] : 0.f;
    }
    __syncthreads();

    for (int g = tid; g < 512; g += 256) {
        int n = g >> 3, ch = g & 7;
        int gn = n0out + n0 + n;
        int bn = gn >> 7, r = gn & 127;
        size_t base = pk1_rowseg(KC, bn, blockIdx.y, r);
        int w = (ch ^ (r & 7)) << 3;
        union { uint4 v; __half b[8]; } uh;
#pragma unroll
        for (int j = 0; j < 8; ++j)
            uh.b[j] = __float2half_rn(sm[ch * 8 + j][n]);
        *(uint4*)(Bl + base + w) = uh.v;
    }
}

// ======================= HMMA GEMM (fp16, 2-term: AhB + AlB) =======================
#define EPI_NONE 0
#define EPI_GELU_PK 2
#define EPI_RES 3

#define STAGES 3
#define HG_SMEM_128 (STAGES * (32768 + 16384))
#define HG_SMEM_64  (STAGES * (16384 + 16384))

template<int EPI, int IMS>
__global__ __launch_bounds__(256, 1)
void hgemm(const __half* __restrict__ Apk,
           const __half* __restrict__ Bpk,
           const float* __restrict__ bias,
           const float* __restrict__ Res,
           float* __restrict__ outf,
           __half* __restrict__ outpk,
           int N, int K, int Nl) {
    constexpr int ABYTES = IMS * 8192;     // BM rows x 256B
    constexpr int BBYTES = 16384;          // 128 rows x 128B
    constexpr int SSTRIDE = ABYTES + BBYTES;
    extern __shared__ __align__(1024) char smem[];
    __shared__ __align__(8) uint64_t s_full[STAGES];

    int tid = threadIdx.x;
    int lane = tid & 31, w = tid >> 5;
    int wm = w & 1, wn = w >> 1;      // warp grid 2(M) x 4(N)
    int bm = blockIdx.y, bn = blockIdx.x;
    int KC = K >> 6;
    uint32_t sbase = smem_u32(smem);
    uint32_t mb0 = smem_u32(&s_full[0]);

    int blkA = (IMS == 4) ? bm : (bm >> 1);
    int roff = (IMS == 4) ? 0 : ((bm & 1) << 6);

    if (tid == 0) {
#pragma unroll
        for (int s = 0; s < STAGES; ++s) MBAR_INIT(mb0 + s * 8, 1);
    }
    __syncthreads();

    float acc[IMS][4][4];
#pragma unroll
    for (int i = 0; i < IMS; ++i)
#pragma unroll
        for (int j = 0; j < 4; ++j)
#pragma unroll
            for (int q = 0; q < 4; ++q) acc[i][j][q] = 0.f;

    const int la15 = lane & 15, lahi = lane >> 4;
    const int bmx = lane >> 3;
    const int brow_base = wn * 32 + ((bmx >> 1) << 3) + (lane & 7);
    const int bcs = bmx & 1;

    if (tid == 0) {
#pragma unroll
        for (int c = 0; c < STAGES - 1; ++c) {
            uint32_t m = mb0 + c * 8;
            MBAR_EXPECT_TX(m, SSTRIDE);
            bulk_g2s(sbase + c * SSTRIDE,
                     Apk + (((size_t)(blkA * KC + c)) * 128 + roff) * 128, ABYTES, m);
            bulk_g2s(sbase + c * SSTRIDE + ABYTES,
                     Bpk + ((size_t)bn * KC + c) * 8192, BBYTES, m);
        }
    }

    for (int c = 0; c < KC; ++c) {
        int s = c % STAGES;
        mbar_wait(mb0 + s * 8, (c / STAGES) & 1);

        if (tid == 0) {
            int cn = c + STAGES - 1;
            if (cn < KC) {
                int sn = cn % STAGES;
                uint32_t m = mb0 + sn * 8;
                MBAR_EXPECT_TX(m, SSTRIDE);
                bulk_g2s(sbase + sn * SSTRIDE,
                         Apk + (((size_t)(blkA * KC + cn)) * 128 + roff) * 128, ABYTES, m);
                bulk_g2s(sbase + sn * SSTRIDE + ABYTES,
                         Bpk + ((size_t)bn * KC + cn) * 8192, BBYTES, m);
            }
        }

        uint32_t Ab = sbase + s * SSTRIDE;
        uint32_t Bb = Ab + ABYTES;

#pragma unroll
        for (int kh = 0; kh < 4; ++kh) {
            uint32_t af[2][IMS][4];   // [plane][im][4]
            uint32_t bf_[4][2];
#pragma unroll
            for (int im = 0; im < IMS; ++im) {
                int r = wm * (IMS * 16) + im * 16 + la15;
                int cch = kh * 2 + lahi;
                uint32_t off = (uint32_t)(r * 256 + (((cch ^ (r & 7))) << 4));
                ldsm4(af[0][im], Ab + off);
                ldsm4(af[1][im], Ab + off + 128);
            }
#pragma unroll
            for (int g2 = 0; g2 < 2; ++g2) {
                int nr = brow_base + g2 * 16;
                int cch = kh * 2 + bcs;
                uint32_t off = (uint32_t)(nr * 128 + (((cch ^ (nr & 7))) << 4));
                uint32_t t4[4];
                ldsm4(t4, Bb + off);
                bf_[g2 * 2][0]     = t4[0];
                bf_[g2 * 2][1]     = t4[1];
                bf_[g2 * 2 + 1][0] = t4[2];
                bf_[g2 * 2 + 1][1] = t4[3];
            }
#pragma unroll
            for (int im = 0; im < IMS; ++im)
#pragma unroll
                for (int in_ = 0; in_ < 4; ++in_) {
                    mma16816h(acc[im][in_], af[0][im], bf_[in_]);
                    mma16816h(acc[im][in_], af[1][im], bf_[in_]);
                }
        }
        __syncthreads();
    }

    // ---------------- epilogue ----------------
    int r0 = bm * (IMS * 32) + wm * (IMS * 16) + (lane >> 2);
    int c0base = bn * 128 + wn * 32 + 2 * (lane & 3);
    int KCo = N >> 6;

#pragma unroll
    for (int im = 0; im < IMS; ++im) {
#pragma unroll
        for (int half = 0; half < 2; ++half) {
            int row = r0 + im * 16 + half * 8;
#pragma unroll
            for (int in_ = 0; in_ < 4; ++in_) {
                int col = c0base + in_ * 8;
                float v0 = acc[im][in_][half * 2 + 0];
                float v1 = acc[im][in_][half * 2 + 1];
                if (EPI == EPI_NONE) {
                    *(float2*)(outf + (size_t)row * Nl + col) = make_float2(v0, v1);
                } else if (EPI == EPI_RES) {
                    const float* rr = Res + (size_t)row * Nl + col;
                    v0 += bias[col]     + rr[0];
                    v1 += bias[col + 1] + rr[1];
                    *(float2*)(outf + (size_t)row * Nl + col) = make_float2(v0, v1);
                } else if (EPI == EPI_GELU_PK) {
                    v0 += bias[col];
                    v1 += bias[col + 1];
                    v0 = 0.5f * v0 * (1.0f + erff(v0 * 0.7071067811865476f));
                    v1 = 0.5f * v1 * (1.0f + erff(v1 * 0.7071067811865476f));
                    __half h0 = __float2half_rn(v0);
                    __half h1 = __float2half_rn(v1);
                    __half l0 = __float2half_rn(v0 - __half2float(h0));
                    __half l1 = __float2half_rn(v1 - __half2float(h1));
                    int blk = row >> 7, r = row & 127;
                    size_t base = pk_rowseg(KCo, blk, col >> 6, r);
                    int wi = pk_within(r, col & 63);
                    *(__half2*)(outpk + base + wi)      = __half2(h0, h1);
                    *(__half2*)(outpk + base + 64 + wi) = __half2(l0, l1);
                }
            }
        }
    }
}

// ======================= LM head GEMM (single-pass fp16) =======================
#define HEAD_SMEM (STAGES * (16384 + 16384))

__global__ __launch_bounds__(256, 1)
void hgemm_head(const __half* __restrict__ Apk,
                const __half* __restrict__ Bpk,
                const float* __restrict__ bias,
                float* __restrict__ outf,
                int N, int K, int Nl) {
    constexpr int ABYTES = 16384;
    constexpr int BBYTES = 16384;
    constexpr int SSTRIDE = ABYTES + BBYTES;
    extern __shared__ __align__(1024) char smem[];
    __shared__ __align__(8) uint64_t s_full[STAGES];

    int tid = threadIdx.x;
    int lane = tid & 31, w = tid >> 5;
    int wm = w & 1, wn = w >> 1;
    int bm = blockIdx.y, bn = blockIdx.x;
    int KC = K >> 6;
    uint32_t sbase = smem_u32(smem);
    uint32_t mb0 = smem_u32(&s_full[0]);

    if (tid == 0) {
#pragma unroll
        for (int s = 0; s < STAGES; ++s) MBAR_INIT(mb0 + s * 8, 1);
    }
    __syncthreads();

    float acc[4][4][4];
#pragma unroll
    for (int i = 0; i < 4; ++i)
#pragma unroll
        for (int j = 0; j < 4; ++j)
#pragma unroll
            for (int q = 0; q < 4; ++q) acc[i][j][q] = 0.f;

    const int la15 = lane & 15, lahi = lane >> 4;
    const int bmx = lane >> 3;
    const int brow_base = wn * 32 + ((bmx >> 1) << 3) + (lane & 7);
    const int bcs = bmx & 1;

    if (tid == 0) {
#pragma unroll
        for (int c = 0; c < STAGES - 1; ++c) {
            uint32_t m = mb0 + c * 8;
            MBAR_EXPECT_TX(m, SSTRIDE);
            bulk_g2s(sbase + c * SSTRIDE,
                     Apk + ((size_t)bm * KC + c) * 8192, ABYTES, m);
            bulk_g2s(sbase + c * SSTRIDE + ABYTES,
                     Bpk + ((size_t)bn * KC + c) * 8192, BBYTES, m);
        }
    }

    for (int c = 0; c < KC; ++c) {
        int s = c % STAGES;
        mbar_wait(mb0 + s * 8, (c / STAGES) & 1);

        if (tid == 0) {
            int cn = c + STAGES - 1;
            if (cn < KC) {
                int sn = cn % STAGES;
                uint32_t m = mb0 + sn * 8;
                MBAR_EXPECT_TX(m, SSTRIDE);
                bulk_g2s(sbase + sn * SSTRIDE,
                         Apk + ((size_t)bm * KC + cn) * 8192, ABYTES, m);
                bulk_g2s(sbase + sn * SSTRIDE + ABYTES,
                         Bpk + ((size_t)bn * KC + cn) * 8192, BBYTES, m);
            }
        }

        uint32_t Ab = sbase + s * SSTRIDE;
        uint32_t Bb = Ab + ABYTES;

#pragma unroll
        for (int kh = 0; kh < 4; ++kh) {
            uint32_t af[4][4];
            uint32_t bf_[4][2];
#pragma unroll
            for (int im = 0; im < 4; ++im) {
                int r = wm * 64 + im * 16 + la15;
                int cch = kh * 2 + lahi;
                uint32_t off = (uint32_t)(r * 128 + (((cch ^ (r & 7))) << 4));
                ldsm4(af[im], Ab + off);
            }
#pragma unroll
            for (int g2 = 0; g2 < 2; ++g2) {
                int nr = brow_base + g2 * 16;
                int cch = kh * 2 + bcs;
                uint32_t off = (uint32_t)(nr * 128 + (((cch ^ (nr & 7))) << 4));
                uint32_t t4[4];
                ldsm4(t4, Bb + off);
                bf_[g2 * 2][0]     = t4[0];
                bf_[g2 * 2][1]     = t4[1];
                bf_[g2 * 2 + 1][0] = t4[2];
                bf_[g2 * 2 + 1][1] = t4[3];
            }
#pragma unroll
            for (int im = 0; im < 4; ++im)
#pragma unroll
                for (int in_ = 0; in_ < 4; ++in_)
                    mma16816h(acc[im][in_], af[im], bf_[in_]);
        }
        __syncthreads();
    }

    int r0 = bm * 128 + wm * 64 + (lane >> 2);
    int c0base = bn * 128 + wn * 32 + 2 * (lane & 3);
#pragma unroll
    for (int im = 0; im < 4; ++im) {
#pragma unroll
        for (int half = 0; half < 2; ++half) {
            int row = r0 + im * 16 + half * 8;
#pragma unroll
            for (int in_ = 0; in_ < 4; ++in_) {
                int col = c0base + in_ * 8;
                float v0 = acc[im][in_][half * 2 + 0];
                float v1 = acc[im][in_][half * 2 + 1];
                if (col < Nl)     outf[(size_t)row * Nl + col]     = v0 + bias[col];
                if (col + 1 < Nl) outf[(size_t)row * Nl + col + 1] = v1 + bias[col + 1];
            }
        }
    }
}

// ---------------- tiled causal attention: 64 q-rows per block ----------------
#define ATT_PAD 68
#define ATT_ROW (64 * ATT_PAD)
#define ATT_SMEM (4 * ATT_ROW * 4)

__global__ __launch_bounds__(256)
void attn_kernel(const float* __restrict__ QKV,
                 __half* __restrict__ Opk) {
    extern __shared__ float asm_[];
    float* sq = asm_;
    float* sk = asm_ + ATT_ROW;
    float* sv = asm_ + 2 * ATT_ROW;
    float* sp = asm_ + 3 * ATT_ROW;

    int tid = threadIdx.x;
    int q0 = blockIdx.x * 64;
    int hh = blockIdx.y;
    int b  = blockIdx.z;
    int qr = tid >> 2, dg = tid & 3;
    int qg = q0 + qr;

    const float scale = rsqrtf((float)CC);

    {
        int r = tid >> 4, c4 = (tid & 15) * 4;
#pragma unroll
        for (int it = 0; it < 4; ++it, r += 16) {
            *(float4*)&sq[r * ATT_PAD + c4] =
                *(const float4*)(QKV + ((size_t)(b * TT + q0 + r)) * NQKV + hh * DD + c4);
        }
    }

    float m = -INFINITY, l = 0.f;
    float acc[16];
#pragma unroll
    for (int i = 0; i < 16; ++i) acc[i] = 0.f;

    for (int j0 = 0; j0 <= q0; j0 += 64) {
        __syncthreads();
        {
            int r = tid >> 4, c4 = (tid & 15) * 4;
#pragma unroll
            for (int it = 0; it < 4; ++it, r += 16) {
                size_t rb = ((size_t)(b * TT + j0 + r)) * NQKV + hh * DD + c4;
                *(float4*)&sk[r * ATT_PAD + c4] = *(const float4*)(QKV + rb + CC);
                *(float4*)&sv[r * ATT_PAD + c4] = *(const float4*)(QKV + rb + 2 * CC);
            }
        }
        __syncthreads();

        float s[16];
#pragma unroll
        for (int jj = 0; jj < 16; ++jj) s[jj] = 0.f;
        const float* qrow = sq + qr * ATT_PAD;
#pragma unroll
        for (int k4 = 0; k4 < 16; ++k4) {
            float4 qv = *(const float4*)(qrow + k4 * 4);
#pragma unroll
            for (int jj = 0; jj < 16; ++jj) {
                int j = jj * 4 + dg;
                float4 kv = *(const float4*)(sk + j * ATT_PAD + k4 * 4);
                s[jj] = fmaf(qv.x, kv.x, s[jj]);
                s[jj] = fmaf(qv.y, kv.y, s[jj]);
                s[jj] = fmaf(qv.z, kv.z, s[jj]);
                s[jj] = fmaf(qv.w, kv.w, s[jj]);
            }
        }

        float tmax = -INFINITY;
#pragma unroll
        for (int jj = 0; jj < 16; ++jj) {
            int j = jj * 4 + dg;
            s[jj] = (j0 + j <= qg) ? s[jj] * scale : -INFINITY;
            tmax = fmaxf(tmax, s[jj]);
        }
        tmax = fmaxf(tmax, __shfl_xor_sync(0xFFFFFFFF, tmax, 1));
        tmax = fmaxf(tmax, __shfl_xor_sync(0xFFFFFFFF, tmax, 2));

        float newm = fmaxf(m, tmax);
        float corr = __expf(m - newm);
        float lp = 0.f;
#pragma unroll
        for (int jj = 0; jj < 16; ++jj) {
            int j = jj * 4 + dg;
            float p = __expf(s[jj] - newm);
            sp[qr * ATT_PAD + j] = p;
            lp += p;
        }
        lp += __shfl_xor_sync(0xFFFFFFFF, lp, 1);
        lp += __shfl_xor_sync(0xFFFFFFFF, lp, 2);
        l = l * corr + lp;
        m = newm;
#pragma unroll
        for (int i = 0; i < 16; ++i) acc[i] *= corr;

        __syncthreads();

        const float* prow = sp + qr * ATT_PAD;
#pragma unroll 8
        for (int j = 0; j < 64; ++j) {
            float pj = prow[j];
            const float* vrow = sv + j * ATT_PAD + dg * 16;
            float4 v0 = *(const float4*)(vrow);
            float4 v1 = *(const float4*)(vrow + 4);
            float4 v2 = *(const float4*)(vrow + 8);
            float4 v3 = *(const float4*)(vrow + 12);
            acc[0]  = fmaf(pj, v0.x, acc[0]);  acc[1]  = fmaf(pj, v0.y, acc[1]);
            acc[2]  = fmaf(pj, v0.z, acc[2]);  acc[3]  = fmaf(pj, v0.w, acc[3]);
            acc[4]  = fmaf(pj, v1.x, acc[4]);  acc[5]  = fmaf(pj, v1.y, acc[5]);
            acc[6]  = fmaf(pj, v1.z, acc[6]);  acc[7]  = fmaf(pj, v1.w, acc[7]);
            acc[8]  = fmaf(pj, v2.x, acc[8]);  acc[9]  = fmaf(pj, v2.y, acc[9]);
            acc[10] = fmaf(pj, v2.z, acc[10]); acc[11] = fmaf(pj, v2.w, acc[11]);
            acc[12] = fmaf(pj, v3.x, acc[12]); acc[13] = fmaf(pj, v3.y, acc[13]);
            acc[14] = fmaf(pj, v3.z, acc[14]); acc[15] = fmaf(pj, v3.w, acc[15]);
        }
    }

    float inv = 1.0f / l;
    int rowg = b * TT + qg;
    int blk = rowg >> 7, r = rowg & 127;
    size_t base = pk_rowseg(12, blk, hh, r);
#pragma unroll
    for (int dd = 0; dd < 16; dd += 2) {
        int d = dg * 16 + dd;
        float v0 = acc[dd] * inv;
        float v1 = acc[dd + 1] * inv;
        __half h0 = __float2half_rn(v0);
        __half h1 = __float2half_rn(v1);
        __half l0 = __float2half_rn(v0 - __half2float(h0));
        __half l1 = __float2half_rn(v1 - __half2float(h1));
        int wi = pk_within(r, d);
        *(__half2*)(Opk + base + wi)      = __half2(h0, h1);
        *(__half2*)(Opk + base + 64 + wi) = __half2(l0, l1);
    }
}

// ======================= launch =======================
extern "C" void kernel_launch(void* const* d_in, const int* in_sizes, int n_in,
                              void* d_out, int out_size) {
    const int*   tokens = (const int*)  d_in[0];
    const float* wte    = (const float*)d_in[1];
    const float* wpe    = (const float*)d_in[2];
    const float* Wq     = (const float*)d_in[3];
    const float* Wk     = (const float*)d_in[4];
    const float* Wv     = (const float*)d_in[5];
    const float* Wo     = (const float*)d_in[6];
    const float* bo     = (const float*)d_in[7];
    const float* ln1g   = (const float*)d_in[8];
    const float* ln1b   = (const float*)d_in[9];
    const float* ln2g   = (const float*)d_in[10];
    const float* ln2b   = (const float*)d_in[11];
    const float* W1     = (const float*)d_in[12];
    const float* b1     = (const float*)d_in[13];
    const float* W2     = (const float*)d_in[14];
    const float* b2     = (const float*)d_in[15];
    const float* lnfg   = (const float*)d_in[16];
    const float* lnfb   = (const float*)d_in[17];
    const float* Wh     = (const float*)d_in[18];
    const float* bh     = (const float*)d_in[19];
    float* out = (float*)d_out;

    static bool attrs_set = false;
    if (!attrs_set) {
        cudaFuncSetAttribute(hgemm<EPI_NONE, 4>,    cudaFuncAttributeMaxDynamicSharedMemorySize, HG_SMEM_128);
        cudaFuncSetAttribute(hgemm<EPI_GELU_PK, 4>, cudaFuncAttributeMaxDynamicSharedMemorySize, HG_SMEM_128);
        cudaFuncSetAttribute(hgemm<EPI_RES, 2>,     cudaFuncAttributeMaxDynamicSharedMemorySize, HG_SMEM_64);
        cudaFuncSetAttribute(hgemm_head,            cudaFuncAttributeMaxDynamicSharedMemorySize, HEAD_SMEM);
        cudaFuncSetAttribute(attn_kernel,           cudaFuncAttributeMaxDynamicSharedMemorySize, ATT_SMEM);
        attrs_set = true;
    }

    float *h, *qkv;
    __half *xpk, *opk, *mpk, *wqkvpk, *wopk, *w1pk, *w2pk, *whpk;
    cudaGetSymbolAddress((void**)&h,      g_h);
    cudaGetSymbolAddress((void**)&qkv,    g_qkv);
    cudaGetSymbolAddress((void**)&xpk,    g_xpk);
    cudaGetSymbolAddress((void**)&opk,    g_opk);
    cudaGetSymbolAddress((void**)&mpk,    g_mpk);
    cudaGetSymbolAddress((void**)&wqkvpk, g_wqkvpk);
    cudaGetSymbolAddress((void**)&wopk,   g_wopk);
    cudaGetSymbolAddress((void**)&w1pk,   g_w1pk);
    cudaGetSymbolAddress((void**)&w2pk,   g_w2pk);
    cudaGetSymbolAddress((void**)&whpk,   g_whpk);

    dim3 gQKV(NQKV / 128, MM / 128);   // (18, 32)
    dim3 gC64(CC / 128, MM / 64);      // (6, 64)  BM=64
    dim3 gF(FF / 128, MM / 128);       // (24, 32)
    dim3 gV(VPAD / 128, MM / 128);     // (393, 32)

    // batched pack grids: z = layer
    dim3 pCC(12, 12, LL);
    dim3 pW1(48, 12, LL);
    dim3 pW2(12, 48, LL);
    dim3 pWh(786, 12, 1);

    const size_t WQKV_L = (size_t)NQKV * CC;
    const size_t WO_L   = (size_t)CC * CC;
    const size_t W1_L   = (size_t)FF * CC;
    const size_t W2_L   = (size_t)CC * FF;

    embed_kernel<<<MM, 256>>>(tokens, wte, wpe, h);
    // pack ALL weights up front, batched over layers
    pack_w16_kernel<<<pWh, 256>>>(Wh, whpk, CC, VV, 0, 0, 0);
    pack_w16_kernel<<<pCC, 256>>>(Wq, wqkvpk, CC, CC, 0,    (size_t)CC * CC, WQKV_L);
    pack_w16_kernel<<<pCC, 256>>>(Wk, wqkvpk, CC, CC, 768,  (size_t)CC * CC, WQKV_L);
    pack_w16_kernel<<<pCC, 256>>>(Wv, wqkvpk, CC, CC, 1536, (size_t)CC * CC, WQKV_L);
    pack_w16_kernel<<<pCC, 256>>>(Wo, wopk, CC, CC, 0,      (size_t)CC * CC, WO_L);
    pack_w16_kernel<<<pW1, 256>>>(W1, w1pk, CC, FF, 0,      (size_t)CC * FF, W1_L);
    pack_w16_kernel<<<pW2, 256>>>(W2, w2pk, FF, CC, 0,      (size_t)FF * CC, W2_L);

    for (int l = 0; l < LL; l++) {
        ln_pk_kernel<<<MM / 8, 256>>>(h, ln1g + l * CC, ln1b + l * CC, xpk);
        hgemm<EPI_NONE, 4><<<gQKV, 256, HG_SMEM_128>>>(xpk, wqkvpk + l * WQKV_L,
                                                       nullptr, nullptr,
                                                       qkv, nullptr, NQKV, CC, NQKV);

        attn_kernel<<<dim3(TT / 64, HH, BB), 256, ATT_SMEM>>>(qkv, opk);

        hgemm<EPI_RES, 2><<<gC64, 256, HG_SMEM_64>>>(opk, wopk + l * WO_L,
                                                     bo + l * CC, h,
                                                     h, nullptr, CC, CC, CC);

        ln_pk_kernel<<<MM / 8, 256>>>(h, ln2g + l * CC, ln2b + l * CC, xpk);
        hgemm<EPI_GELU_PK, 4><<<gF, 256, HG_SMEM_128>>>(xpk, w1pk + l * W1_L,
                                                        b1 + l * FF, nullptr,
                                                        nullptr, mpk, FF, CC, FF);
        hgemm<EPI_RES, 2><<<gC64, 256, HG_SMEM_64>>>(mpk, w2pk + l * W2_L,
                                                     b2 + l * CC, h,
                                                     h, nullptr, CC, FF, CC);
    }

    ln_pk16_kernel<<<MM / 8, 256>>>(h, lnfg, lnfb, xpk);
    hgemm_head<<<gV, 256, HEAD_SMEM>>>(xpk, whpk, bh, out, VPAD, CC, VV);
}